// round 13
// baseline (speedup 1.0000x reference)
#include <cuda_runtime.h>
#include <cuda_fp16.h>
#include <math.h>
#include <stdint.h>

#define BSZ 2
#define LEN 4096
#define TT (BSZ*LEN)          // 8192 tokens
#define DM 768
#define DI 1536
#define DS 16
#define NH 24
#define HD 64
#define CD 1568               // DI + 2*DS
#define DP 3128               // 2*DI + 2*DS + NH
#define NP1 3200              // DP padded to 128
#define NC 64                 // chunks
#define CH 64                 // chunk length (LEN/NC)

// ---------------- scratch (static device arrays; no runtime alloc) ----------
__device__ __align__(16) __half g_zx16[(size_t)TT*DP];   // GEMM1 out: z|xBC|dt (fp16)
__device__ __align__(16) float g_dtr[TT*NH];             // raw dt cols (fp32 side-store)
__device__ float g_dt[TT*NH];
__device__ float g_dA[TT*NH];
__device__ __align__(16) __half g_xbc16[(size_t)TT*CD];  // conv output (fp16)
__device__ __align__(16) __half g_y16[(size_t)TT*DI];    // scan output y (fp16)
__device__ __align__(16) float g_hl[BSZ*NH*NC*HD*DS];
__device__ __align__(16) float g_hs[BSZ*NH*NC*HD*DS];
__device__ float g_P[BSZ*NH*NC];
// fp16 GEMM operand buffers
__device__ __align__(16) __half g_u16[(size_t)TT*DM];
__device__ __align__(16) __half g_W1[(size_t)NP1*DM];
__device__ __align__(16) __half g_g16[(size_t)TT*DI];
__device__ __align__(16) __half g_W2[(size_t)DM*DI];

// ---------------- weight convert (both weights, one launch) -----------------
#define W1PAD (NP1*DM)
#define W2N   (DM*DI)
__global__ void k_cvt2(const float* __restrict__ W1, const float* __restrict__ W2) {
    int i = blockIdx.x * 256 + threadIdx.x;
    if (i < W1PAD) {
        g_W1[i] = __float2half_rn((i < DP*DM) ? W1[i] : 0.f);
    } else if (i < W1PAD + W2N) {
        int j = i - W1PAD;
        g_W2[j] = __float2half_rn(W2[j]);
    }
}

// ---------------- layernorm -> fp16 ------------------------------------------
__global__ void k_ln(const float* __restrict__ x, const float* __restrict__ w,
                     const float* __restrict__ bb) {
    int row = blockIdx.x;
    int tid = threadIdx.x;
    const float* xr = x + (size_t)row * DM;
    float v0 = xr[tid], v1 = xr[tid + 256], v2 = xr[tid + 512];
    float s  = v0 + v1 + v2;
    float sq = v0*v0 + v1*v1 + v2*v2;
    __shared__ float sh[16];
    #pragma unroll
    for (int m = 16; m; m >>= 1) {
        s  += __shfl_xor_sync(0xffffffffu, s,  m);
        sq += __shfl_xor_sync(0xffffffffu, sq, m);
    }
    if ((tid & 31) == 0) { sh[tid >> 5] = s; sh[8 + (tid >> 5)] = sq; }
    __syncthreads();
    if (tid < 32) {
        float a  = (tid < 8) ? sh[tid]     : 0.f;
        float b2 = (tid < 8) ? sh[8 + tid] : 0.f;
        #pragma unroll
        for (int m = 4; m; m >>= 1) {
            a  += __shfl_xor_sync(0xffffffffu, a,  m);
            b2 += __shfl_xor_sync(0xffffffffu, b2, m);
        }
        if (tid == 0) { sh[0] = a; sh[8] = b2; }
    }
    __syncthreads();
    float mu  = sh[0] * (1.f / DM);
    float var = sh[8] * (1.f / DM) - mu * mu;
    float inv = rsqrtf(var + 1e-5f);
    size_t base = (size_t)row * DM;
    g_u16[base + tid]       = __float2half_rn((v0 - mu) * inv * w[tid]       + bb[tid]);
    g_u16[base + tid + 256] = __float2half_rn((v1 - mu) * inv * w[tid + 256] + bb[tid + 256]);
    g_u16[base + tid + 512] = __float2half_rn((v2 - mu) * inv * w[tid + 512] + bb[tid + 512]);
}

// ============================================================================
// fp16 single-pass HMMA NT GEMM. CTA tile 128x128x32, 8 warps, 4-stage cp.async.
// mode 0: C (float) = A*B^T + R.
// mode 1: H (half)  = A*B^T, plus fp32 side-store of dt cols [DI+CD, DP).
// ============================================================================
#define SP 40                     // smem row pitch in halves (32 data + 8 pad)
#define A_ELE (128*SP)
#define OFF_A 0
#define OFF_B (A_ELE*2)
#define STAGE_B (2*A_ELE*2)       // 20480 bytes
#define NSTG 4
#define GSMEM (NSTG*STAGE_B)      // 81920 bytes

__device__ __forceinline__ uint32_t smaddr(const void* p) {
    return (uint32_t)__cvta_generic_to_shared(p);
}
#define CPA(d, s) asm volatile("cp.async.cg.shared.global [%0], [%1], 16;\n" :: "r"(d), "l"(s))
#define CPCOMMIT() asm volatile("cp.async.commit_group;\n")
#define CPWAIT2() asm volatile("cp.async.wait_group 2;\n")
#define LDSM4(r0,r1,r2,r3,a) asm volatile( \
    "ldmatrix.sync.aligned.m8n8.x4.shared.b16 {%0,%1,%2,%3}, [%4];\n" \
    : "=r"(r0),"=r"(r1),"=r"(r2),"=r"(r3) : "r"(a))
#define MMAH(d, a, b0, b1) \
  asm volatile("mma.sync.aligned.m16n8k16.row.col.f32.f16.f16.f32 " \
      "{%0,%1,%2,%3}, {%4,%5,%6,%7}, {%8,%9}, {%0,%1,%2,%3};\n" \
      : "+f"(d[0]), "+f"(d[1]), "+f"(d[2]), "+f"(d[3]) \
      : "r"(a[0]), "r"(a[1]), "r"(a[2]), "r"(a[3]), "r"(b0), "r"(b1))

__global__ void __launch_bounds__(256, 2)
k_gemm_h(const __half* __restrict__ A, const __half* __restrict__ B,
         float* __restrict__ C, __half* __restrict__ H,
         const float* __restrict__ R,
         int M, int N, int K, int mode) {
    extern __shared__ __half sm[];
    const int tid = threadIdx.x;
    const int warp = tid >> 5, lane = tid & 31;
    const int wm = (warp & 1) * 64;
    const int wn = (warp >> 1) * 32;
    const int bm = blockIdx.y * 128, bn = blockIdx.x * 128;
    const int nIter = K >> 5;
    const uint32_t smb = smaddr(sm);

    const int a_r = lane & 15, a_k = (lane >> 4) << 3;
    const int b_r = (lane & 7) + ((lane >> 4) << 3);
    const int b_k = ((lane >> 3) & 1) << 3;

    float acc[4][4][4];
    #pragma unroll
    for (int i = 0; i < 4; i++)
        #pragma unroll
        for (int j = 0; j < 4; j++)
            #pragma unroll
            for (int k = 0; k < 4; k++) acc[i][j][k] = 0.f;

    #define ISSUE(kt) do {                                                     \
        int _b = (kt) & (NSTG - 1), _k = (kt) << 5;                            \
        uint32_t _sb = smb + (uint32_t)_b * STAGE_B;                           \
        _Pragma("unroll")                                                      \
        for (int _i = 0; _i < 2; _i++) {                                       \
            int _idx = tid + 256 * _i;                                         \
            int _r = _idx >> 2, _c = (_idx & 3) << 3;                          \
            uint32_t _d = (uint32_t)(_r * SP + _c) * 2;                        \
            CPA(_sb + OFF_A + _d, A + (size_t)(bm + _r) * K + _k + _c);        \
            CPA(_sb + OFF_B + _d, B + (size_t)(bn + _r) * K + _k + _c);        \
        }                                                                      \
        CPCOMMIT();                                                            \
    } while (0)

    ISSUE(0);
    ISSUE(1);
    ISSUE(2);

    for (int kt = 0; kt < nIter; kt++) {
        CPWAIT2();
        __syncthreads();
        const int s = kt & (NSTG - 1);
        const uint32_t sb = smb + (uint32_t)s * STAGE_B;

        #pragma unroll
        for (int sub = 0; sub < 32; sub += 16) {
            unsigned bh[2][4];
            #pragma unroll
            for (int p = 0; p < 2; p++) {
                uint32_t ba = sb + OFF_B +
                    (uint32_t)((wn + p*16 + b_r) * SP + sub + b_k) * 2;
                LDSM4(bh[p][0], bh[p][1], bh[p][2], bh[p][3], ba);
            }
            #pragma unroll
            for (int mt = 0; mt < 4; mt++) {
                unsigned ah[4];
                uint32_t aa = sb + OFF_A +
                    (uint32_t)((wm + mt*16 + a_r) * SP + sub + a_k) * 2;
                LDSM4(ah[0], ah[1], ah[2], ah[3], aa);
                #pragma unroll
                for (int p = 0; p < 2; p++) {
                    MMAH(acc[mt][2*p],   ah, bh[p][0], bh[p][1]);
                    MMAH(acc[mt][2*p+1], ah, bh[p][2], bh[p][3]);
                }
            }
        }

        int nk = kt + 3;
        if (nk < nIter) { ISSUE(nk); }
        else            { CPCOMMIT(); }
    }

    // epilogue
    const int g = lane >> 2, q = lane & 3;
    #pragma unroll
    for (int mt = 0; mt < 4; mt++) {
        int row0 = bm + wm + mt * 16 + g;
        #pragma unroll
        for (int nt = 0; nt < 4; nt++) {
            int col = bn + wn + nt * 8 + 2 * q;
            if (col < N) {
                float2 v0, v1;
                v0.x = acc[mt][nt][0]; v0.y = acc[mt][nt][1];
                v1.x = acc[mt][nt][2]; v1.y = acc[mt][nt][3];
                if (mode == 1) {
                    *(__half2*)(H + (size_t)row0 * N + col) =
                        __floats2half2_rn(v0.x, v0.y);
                    *(__half2*)(H + (size_t)(row0 + 8) * N + col) =
                        __floats2half2_rn(v1.x, v1.y);
                    if (col >= DI + CD) {
                        int hcol = col - (DI + CD);
                        *(float2*)&g_dtr[(size_t)row0 * NH + hcol] = v0;
                        *(float2*)&g_dtr[(size_t)(row0 + 8) * NH + hcol] = v1;
                    }
                } else {
                    const float* rr0 = R + (size_t)row0 * N + col;
                    const float* rr1 = R + (size_t)(row0 + 8) * N + col;
                    v0.x += rr0[0]; v0.y += rr0[1];
                    v1.x += rr1[0]; v1.y += rr1[1];
                    *(float2*)(C + (size_t)row0 * N + col) = v0;
                    *(float2*)(C + (size_t)(row0 + 8) * N + col) = v1;
                }
            }
        }
    }
    #undef ISSUE
}

// ---------------- dt = softplus(raw + bias), dA = exp(dt * -exp(A_log)) -----
__global__ void k_dtda(const float* __restrict__ dtb, const float* __restrict__ alog) {
    int i = blockIdx.x * 256 + threadIdx.x;
    if (i >= TT * NH) return;
    int h = i % NH;
    float xv = g_dtr[i] + dtb[h];
    float dt = (xv > 20.f) ? xv : log1pf(expf(xv));
    float A = -expf(alog[h]);
    g_dt[i] = dt;
    g_dA[i] = expf(dt * A);
}

// ---------------- causal depthwise conv(4): smem-tiled, fp16 in/out ----------
#define CT 32
#define CC 224
__global__ void __launch_bounds__(256)
k_conv(const float* __restrict__ cw, const float* __restrict__ cb) {
    __shared__ float sx[(CT + 3) * CC];
    __shared__ float swt[CC * 4];
    __shared__ float sbi[CC];
    int c0 = blockIdx.x * CC;
    int tblk = blockIdx.y;
    int b = (tblk * CT) / LEN;
    int l0 = (tblk * CT) % LEN;
    int tid = threadIdx.x;

    for (int i = tid; i < CC * 4; i += 256) swt[i] = cw[c0 * 4 + i];
    for (int i = tid; i < CC; i += 256)     sbi[i] = cb[c0 + i];
    for (int i = tid; i < (CT + 3) * CC; i += 256) {
        int r = i / CC, c = i % CC;
        int l = l0 - 3 + r;
        sx[i] = (l >= 0)
            ? __half2float(g_zx16[((size_t)(b * LEN + l)) * DP + DI + c0 + c])
            : 0.f;
    }
    __syncthreads();

    for (int i = tid; i < CT * CC; i += 256) {
        int t = i / CC, c = i % CC;
        const float* w4 = &swt[c * 4];
        float acc = sbi[c];
        acc = fmaf(sx[(t + 0) * CC + c], w4[0], acc);
        acc = fmaf(sx[(t + 1) * CC + c], w4[1], acc);
        acc = fmaf(sx[(t + 2) * CC + c], w4[2], acc);
        acc = fmaf(sx[(t + 3) * CC + c], w4[3], acc);
        g_xbc16[((size_t)(b * LEN + l0 + t)) * CD + c0 + c] =
            __float2half_rn(acc / (1.f + expf(-acc)));
    }
}

// ---------------- scan phase 1: thread-per-p, h[16] in registers ------------
__global__ void __launch_bounds__(64)
k_scan1() {
    int c = blockIdx.x, hd = blockIdx.y, b = blockIdx.z;
    int p = threadIdx.x;
    __shared__ float sx[CH * HD];
    __shared__ __align__(16) float sB[CH * DS];
    __shared__ float sdt[CH];
    __shared__ float sdA[CH];
    int t0 = c * CH;
    size_t rb = ((size_t)(b * LEN + t0)) * CD;
    for (int idx = p; idx < CH * HD; idx += 64) {
        int t = idx >> 6, pp = idx & 63;
        sx[idx] = __half2float(g_xbc16[rb + (size_t)t * CD + hd * HD + pp]);
    }
    for (int idx = p; idx < CH * DS; idx += 64) {
        int t = idx >> 4, n = idx & 15;
        sB[idx] = __half2float(g_xbc16[rb + (size_t)t * CD + DI + n]);
    }
    {
        int tg = (b * LEN + t0 + p) * NH + hd;
        sdt[p] = g_dt[tg];
        sdA[p] = g_dA[tg];
    }
    __syncthreads();
    float h[16];
    #pragma unroll
    for (int n = 0; n < 16; n++) h[n] = 0.f;
    float run = 1.f;
    for (int t = 0; t < CH; t++) {
        float dA = sdA[t];
        float s = sdt[t] * sx[t * HD + p];
        run *= dA;
        #pragma unroll
        for (int n = 0; n < 16; n += 4) {
            float4 Bv = *(const float4*)&sB[t * DS + n];
            h[n]   = fmaf(dA, h[n],   s * Bv.x);
            h[n+1] = fmaf(dA, h[n+1], s * Bv.y);
            h[n+2] = fmaf(dA, h[n+2], s * Bv.z);
            h[n+3] = fmaf(dA, h[n+3], s * Bv.w);
        }
    }
    size_t base = ((size_t)((b * NH + hd) * NC + c)) * (HD * DS);
    #pragma unroll
    for (int n = 0; n < 16; n += 4)
        *(float4*)&g_hl[base + p * DS + n] = make_float4(h[n], h[n+1], h[n+2], h[n+3]);
    if (p == 0) g_P[(b * NH + hd) * NC + c] = run;
}

// ---------------- scan phase 2: prefix over chunks, 1 elem/thread -----------
__global__ void __launch_bounds__(256)
k_scan2() {
    int e = blockIdx.x * 256 + threadIdx.x;   // 0..1023
    int bh = blockIdx.y;                       // 0..47
    __shared__ float sP[NC];
    if (threadIdx.x < NC) sP[threadIdx.x] = g_P[bh * NC + threadIdx.x];
    __syncthreads();
    float H = 0.f;
    #pragma unroll 8
    for (int c = 0; c < NC; c++) {
        size_t base = ((size_t)(bh * NC + c)) * (HD * DS);
        g_hs[base + e] = H;
        H = fmaf(sP[c], H, g_hl[base + e]);
    }
}

// ---------------- scan phase 3: thread-per-p, emits y (fp16) ----------------
__global__ void __launch_bounds__(64)
k_scan3(const float* __restrict__ Dp) {
    int c = blockIdx.x, hd = blockIdx.y, b = blockIdx.z;
    int p = threadIdx.x;
    __shared__ float sx[CH * HD];
    __shared__ __align__(16) float sB[CH * DS];
    __shared__ __align__(16) float sC[CH * DS];
    __shared__ float sdt[CH];
    __shared__ float sdA[CH];
    int t0 = c * CH;
    size_t rb = ((size_t)(b * LEN + t0)) * CD;
    for (int idx = p; idx < CH * HD; idx += 64) {
        int t = idx >> 6, pp = idx & 63;
        sx[idx] = __half2float(g_xbc16[rb + (size_t)t * CD + hd * HD + pp]);
    }
    for (int idx = p; idx < CH * DS; idx += 64) {
        int t = idx >> 4, n = idx & 15;
        sB[idx] = __half2float(g_xbc16[rb + (size_t)t * CD + DI + n]);
        sC[idx] = __half2float(g_xbc16[rb + (size_t)t * CD + DI + DS + n]);
    }
    {
        int tg = (b * LEN + t0 + p) * NH + hd;
        sdt[p] = g_dt[tg];
        sdA[p] = g_dA[tg];
    }
    __syncthreads();
    size_t base = ((size_t)((b * NH + hd) * NC + c)) * (HD * DS);
    float h[16];
    #pragma unroll
    for (int n = 0; n < 16; n += 4) {
        float4 v = *(const float4*)&g_hs[base + p * DS + n];
        h[n] = v.x; h[n+1] = v.y; h[n+2] = v.z; h[n+3] = v.w;
    }
    float Dh = Dp[hd];
    for (int t = 0; t < CH; t++) {
        float dA = sdA[t];
        float xv = sx[t * HD + p];
        float s = sdt[t] * xv;
        float y = 0.f;
        #pragma unroll
        for (int n = 0; n < 16; n += 4) {
            float4 Bv = *(const float4*)&sB[t * DS + n];
            float4 Cv = *(const float4*)&sC[t * DS + n];
            h[n]   = fmaf(dA, h[n],   s * Bv.x);
            h[n+1] = fmaf(dA, h[n+1], s * Bv.y);
            h[n+2] = fmaf(dA, h[n+2], s * Bv.z);
            h[n+3] = fmaf(dA, h[n+3], s * Bv.w);
            y += h[n]*Cv.x + h[n+1]*Cv.y + h[n+2]*Cv.z + h[n+3]*Cv.w;
        }
        g_y16[((size_t)(b * LEN + t0 + t)) * DI + hd * HD + p] =
            __float2half_rn(y + Dh * xv);
    }
}

// ---------------- gating + RMSNorm -> fp16 -----------------------------------
__global__ void k_gate(const float* __restrict__ gnw) {
    int row = blockIdx.x, tid = threadIdx.x;
    const __half* yr = g_y16  + (size_t)row * DI;
    const __half* zr = g_zx16 + (size_t)row * DP;
    float gv[6];
    float sq = 0.f;
    #pragma unroll
    for (int i = 0; i < 6; i++) {
        int cc = tid + 256 * i;
        float z = __half2float(zr[cc]);
        float g = __half2float(yr[cc]) * (z / (1.f + expf(-z)));
        gv[i] = g;
        sq += g * g;
    }
    __shared__ float sh[8];
    #pragma unroll
    for (int m = 16; m; m >>= 1) sq += __shfl_xor_sync(0xffffffffu, sq, m);
    if ((tid & 31) == 0) sh[tid >> 5] = sq;
    __syncthreads();
    if (tid < 32) {
        float a = (tid < 8) ? sh[tid] : 0.f;
        #pragma unroll
        for (int m = 4; m; m >>= 1) a += __shfl_xor_sync(0xffffffffu, a, m);
        if (tid == 0) sh[0] = a;
    }
    __syncthreads();
    float inv = rsqrtf(sh[0] * (1.f / DI) + 1e-5f);
    size_t base = (size_t)row * DI;
    #pragma unroll
    for (int i = 0; i < 6; i++) {
        int cc = tid + 256 * i;
        g_g16[base + cc] = __float2half_rn(gv[i] * inv * gnw[cc]);
    }
}

// ---------------- launcher ---------------------------------------------------
extern "C" void kernel_launch(void* const* d_in, const int* in_sizes, int n_in,
                              void* d_out, int out_size) {
    const float* x       = (const float*)d_in[0];
    const float* ln_w    = (const float*)d_in[1];
    const float* ln_b    = (const float*)d_in[2];
    const float* W_in    = (const float*)d_in[3];
    const float* conv_w  = (const float*)d_in[4];
    const float* conv_b  = (const float*)d_in[5];
    const float* dt_bias = (const float*)d_in[6];
    const float* A_log   = (const float*)d_in[7];
    const float* Dv      = (const float*)d_in[8];
    const float* gnw     = (const float*)d_in[9];
    const float* W_out   = (const float*)d_in[10];
    float* out = (float*)d_out;

    __half *pu, *pw1, *pg, *pw2, *pzx;
    cudaGetSymbolAddress((void**)&pzx, g_zx16);
    cudaGetSymbolAddress((void**)&pu,  g_u16);
    cudaGetSymbolAddress((void**)&pw1, g_W1);
    cudaGetSymbolAddress((void**)&pg,  g_g16);
    cudaGetSymbolAddress((void**)&pw2, g_W2);

    cudaFuncSetAttribute(k_gemm_h, cudaFuncAttributeMaxDynamicSharedMemorySize, GSMEM);

    k_cvt2<<<(W1PAD + W2N + 255)/256, 256>>>(W_in, W_out);
    k_ln<<<TT, 256>>>(x, ln_w, ln_b);
    k_gemm_h<<<dim3(NP1/128, TT/128), 256, GSMEM>>>(
        pu, pw1, nullptr, pzx, nullptr, TT, DP, DM, 1);
    k_dtda<<<(TT * NH + 255) / 256, 256>>>(dt_bias, A_log);
    k_conv<<<dim3(CD/CC, TT/CT), 256>>>(conv_w, conv_b);
    k_scan1<<<dim3(NC, NH, BSZ), 64>>>();
    k_scan2<<<dim3(4, BSZ * NH), 256>>>();
    k_scan3<<<dim3(NC, NH, BSZ), 64>>>(Dv);
    k_gate<<<TT, 256>>>(gnw);
    k_gemm_h<<<dim3(DM/128, TT/128), 256, GSMEM>>>(
        pg, pw2, out, nullptr, x, TT, DM, DI, 0);
}

// round 14
// speedup vs baseline: 1.3107x; 1.3107x over previous
#include <cuda_runtime.h>
#include <cuda_fp16.h>
#include <math.h>
#include <stdint.h>

#define BSZ 2
#define LEN 4096
#define TT (BSZ*LEN)          // 8192 tokens
#define DM 768
#define DI 1536
#define DS 16
#define NH 24
#define HD 64
#define CD 1568               // DI + 2*DS
#define DP 3128               // 2*DI + 2*DS + NH
#define NP1 3200              // DP padded to 128
#define NC 64                 // chunks
#define CH 64                 // chunk length (LEN/NC)

// ---------------- scratch (static device arrays; no runtime alloc) ----------
__device__ __align__(16) float g_zx[(size_t)TT*DP];
__device__ __align__(16) float g_xbc[(size_t)TT*CD];
__device__ float g_dt[TT*NH];
__device__ float g_dA[TT*NH];
__device__ __align__(16) float g_y[(size_t)TT*DI];      // gv after scan3
__device__ __align__(16) float g_hl[BSZ*NH*NC*HD*DS];
__device__ __align__(16) float g_hs[BSZ*NH*NC*HD*DS];
__device__ float g_P[BSZ*NH*NC];
// fp16 operand buffers (16B aligned for cp.async)
__device__ __align__(16) __half g_u16[(size_t)TT*DM];
__device__ __align__(16) __half g_W1[(size_t)NP1*DM];
__device__ __align__(16) __half g_g16[(size_t)TT*DI];
__device__ __align__(16) __half g_W2[(size_t)DM*DI];

// ---------------- weight convert (both weights, one launch) -----------------
#define W1PAD (NP1*DM)
#define W2N   (DM*DI)
__global__ void k_cvt2(const float* __restrict__ W1, const float* __restrict__ W2) {
    int i = blockIdx.x * 256 + threadIdx.x;
    if (i < W1PAD) {
        g_W1[i] = __float2half_rn((i < DP*DM) ? W1[i] : 0.f);
    } else if (i < W1PAD + W2N) {
        int j = i - W1PAD;
        g_W2[j] = __float2half_rn(W2[j]);
    }
}

// ---------------- layernorm -> fp16 ------------------------------------------
__global__ void k_ln(const float* __restrict__ x, const float* __restrict__ w,
                     const float* __restrict__ bb) {
    int row = blockIdx.x;
    int tid = threadIdx.x;
    const float* xr = x + (size_t)row * DM;
    float v0 = xr[tid], v1 = xr[tid + 256], v2 = xr[tid + 512];
    float s  = v0 + v1 + v2;
    float sq = v0*v0 + v1*v1 + v2*v2;
    __shared__ float sh[16];
    #pragma unroll
    for (int m = 16; m; m >>= 1) {
        s  += __shfl_xor_sync(0xffffffffu, s,  m);
        sq += __shfl_xor_sync(0xffffffffu, sq, m);
    }
    if ((tid & 31) == 0) { sh[tid >> 5] = s; sh[8 + (tid >> 5)] = sq; }
    __syncthreads();
    if (tid < 32) {
        float a  = (tid < 8) ? sh[tid]     : 0.f;
        float b2 = (tid < 8) ? sh[8 + tid] : 0.f;
        #pragma unroll
        for (int m = 4; m; m >>= 1) {
            a  += __shfl_xor_sync(0xffffffffu, a,  m);
            b2 += __shfl_xor_sync(0xffffffffu, b2, m);
        }
        if (tid == 0) { sh[0] = a; sh[8] = b2; }
    }
    __syncthreads();
    float mu  = sh[0] * (1.f / DM);
    float var = sh[8] * (1.f / DM) - mu * mu;
    float inv = rsqrtf(var + 1e-5f);
    size_t base = (size_t)row * DM;
    g_u16[base + tid]       = __float2half_rn((v0 - mu) * inv * w[tid]       + bb[tid]);
    g_u16[base + tid + 256] = __float2half_rn((v1 - mu) * inv * w[tid + 256] + bb[tid + 256]);
    g_u16[base + tid + 512] = __float2half_rn((v2 - mu) * inv * w[tid + 512] + bb[tid + 512]);
}

// ============================================================================
// fp16 single-pass HMMA NT GEMM: C[M,N] = A[M,K]*B[N,K]^T (+R).
// CTA tile 128x128x32, 8 warps (warp tile 64x32), 4-stage cp.async, ldmatrix.x4.
// 2 CTAs/SM. M%128==0, K%32==0, B padded so grid-N loads valid; stores col<N.
// ============================================================================
#define SP 40                     // smem row pitch in halves (32 data + 8 pad)
#define A_ELE (128*SP)
#define OFF_A 0
#define OFF_B (A_ELE*2)
#define STAGE_B (2*A_ELE*2)       // 20480 bytes
#define NSTG 4
#define GSMEM (NSTG*STAGE_B)      // 81920 bytes

__device__ __forceinline__ uint32_t smaddr(const void* p) {
    return (uint32_t)__cvta_generic_to_shared(p);
}
#define CPA(d, s) asm volatile("cp.async.cg.shared.global [%0], [%1], 16;\n" :: "r"(d), "l"(s))
#define CPCOMMIT() asm volatile("cp.async.commit_group;\n")
#define CPWAIT2() asm volatile("cp.async.wait_group 2;\n")
#define LDSM4(r0,r1,r2,r3,a) asm volatile( \
    "ldmatrix.sync.aligned.m8n8.x4.shared.b16 {%0,%1,%2,%3}, [%4];\n" \
    : "=r"(r0),"=r"(r1),"=r"(r2),"=r"(r3) : "r"(a))
#define MMAH(d, a, b0, b1) \
  asm volatile("mma.sync.aligned.m16n8k16.row.col.f32.f16.f16.f32 " \
      "{%0,%1,%2,%3}, {%4,%5,%6,%7}, {%8,%9}, {%0,%1,%2,%3};\n" \
      : "+f"(d[0]), "+f"(d[1]), "+f"(d[2]), "+f"(d[3]) \
      : "r"(a[0]), "r"(a[1]), "r"(a[2]), "r"(a[3]), "r"(b0), "r"(b1))

__global__ void __launch_bounds__(256, 2)
k_gemm_h(const __half* __restrict__ A, const __half* __restrict__ B,
         float* __restrict__ C, const float* __restrict__ R,
         int M, int N, int K) {
    extern __shared__ __half sm[];
    const int tid = threadIdx.x;
    const int warp = tid >> 5, lane = tid & 31;
    const int wm = (warp & 1) * 64;        // 2 m-positions
    const int wn = (warp >> 1) * 32;       // 4 n-positions
    const int bm = blockIdx.y * 128, bn = blockIdx.x * 128;
    const int nIter = K >> 5;
    const uint32_t smb = smaddr(sm);

    const int a_r = lane & 15, a_k = (lane >> 4) << 3;
    const int b_r = (lane & 7) + ((lane >> 4) << 3);
    const int b_k = ((lane >> 3) & 1) << 3;

    float acc[4][4][4];
    #pragma unroll
    for (int i = 0; i < 4; i++)
        #pragma unroll
        for (int j = 0; j < 4; j++)
            #pragma unroll
            for (int k = 0; k < 4; k++) acc[i][j][k] = 0.f;

    #define ISSUE(kt) do {                                                     \
        int _b = (kt) & (NSTG - 1), _k = (kt) << 5;                            \
        uint32_t _sb = smb + (uint32_t)_b * STAGE_B;                           \
        _Pragma("unroll")                                                      \
        for (int _i = 0; _i < 2; _i++) {                                       \
            int _idx = tid + 256 * _i;                                         \
            int _r = _idx >> 2, _c = (_idx & 3) << 3;                          \
            uint32_t _d = (uint32_t)(_r * SP + _c) * 2;                        \
            CPA(_sb + OFF_A + _d, A + (size_t)(bm + _r) * K + _k + _c);        \
            CPA(_sb + OFF_B + _d, B + (size_t)(bn + _r) * K + _k + _c);        \
        }                                                                      \
        CPCOMMIT();                                                            \
    } while (0)

    ISSUE(0);
    ISSUE(1);
    ISSUE(2);

    for (int kt = 0; kt < nIter; kt++) {
        CPWAIT2();
        __syncthreads();
        const int s = kt & (NSTG - 1);
        const uint32_t sb = smb + (uint32_t)s * STAGE_B;

        #pragma unroll
        for (int sub = 0; sub < 32; sub += 16) {
            unsigned bh[2][4];
            #pragma unroll
            for (int p = 0; p < 2; p++) {
                uint32_t ba = sb + OFF_B +
                    (uint32_t)((wn + p*16 + b_r) * SP + sub + b_k) * 2;
                LDSM4(bh[p][0], bh[p][1], bh[p][2], bh[p][3], ba);
            }
            #pragma unroll
            for (int mt = 0; mt < 4; mt++) {
                unsigned ah[4];
                uint32_t aa = sb + OFF_A +
                    (uint32_t)((wm + mt*16 + a_r) * SP + sub + a_k) * 2;
                LDSM4(ah[0], ah[1], ah[2], ah[3], aa);
                #pragma unroll
                for (int p = 0; p < 2; p++) {
                    MMAH(acc[mt][2*p],   ah, bh[p][0], bh[p][1]);
                    MMAH(acc[mt][2*p+1], ah, bh[p][2], bh[p][3]);
                }
            }
        }

        int nk = kt + 3;
        if (nk < nIter) { ISSUE(nk); }
        else            { CPCOMMIT(); }
    }

    // epilogue
    const int g = lane >> 2, q = lane & 3;
    #pragma unroll
    for (int mt = 0; mt < 4; mt++) {
        int row0 = bm + wm + mt * 16 + g;
        #pragma unroll
        for (int nt = 0; nt < 4; nt++) {
            int col = bn + wn + nt * 8 + 2 * q;
            if (col < N) {
                float2 v0, v1;
                v0.x = acc[mt][nt][0]; v0.y = acc[mt][nt][1];
                v1.x = acc[mt][nt][2]; v1.y = acc[mt][nt][3];
                if (R) {
                    const float* rr0 = R + (size_t)row0 * N + col;
                    const float* rr1 = R + (size_t)(row0 + 8) * N + col;
                    v0.x += rr0[0]; v0.y += rr0[1];
                    v1.x += rr1[0]; v1.y += rr1[1];
                }
                *(float2*)(C + (size_t)row0 * N + col) = v0;
                *(float2*)(C + (size_t)(row0 + 8) * N + col) = v1;
            }
        }
    }
    #undef ISSUE
}

// ---------------- dt = softplus(raw + bias), dA = exp(dt * -exp(A_log)) -----
__global__ void k_dtda(const float* __restrict__ dtb, const float* __restrict__ alog) {
    int i = blockIdx.x * 256 + threadIdx.x;
    if (i >= TT * NH) return;
    int h = i % NH, t = i / NH;
    float xv = g_zx[(size_t)t * DP + (DI + CD) + h] + dtb[h];
    float dt = (xv > 20.f) ? xv : log1pf(expf(xv));
    float A = -expf(alog[h]);
    g_dt[i] = dt;
    g_dA[i] = expf(dt * A);
}

// ---------------- causal depthwise conv(4): smem-tiled -----------------------
#define CT 32
#define CC 224
__global__ void __launch_bounds__(256)
k_conv(const float* __restrict__ cw, const float* __restrict__ cb) {
    __shared__ float sx[(CT + 3) * CC];
    __shared__ float swt[CC * 4];
    __shared__ float sbi[CC];
    int c0 = blockIdx.x * CC;
    int tblk = blockIdx.y;
    int b = (tblk * CT) / LEN;
    int l0 = (tblk * CT) % LEN;
    int tid = threadIdx.x;

    for (int i = tid; i < CC * 4; i += 256) swt[i] = cw[c0 * 4 + i];
    for (int i = tid; i < CC; i += 256)     sbi[i] = cb[c0 + i];
    for (int i = tid; i < (CT + 3) * CC; i += 256) {
        int r = i / CC, c = i % CC;
        int l = l0 - 3 + r;
        sx[i] = (l >= 0) ? g_zx[((size_t)(b * LEN + l)) * DP + DI + c0 + c] : 0.f;
    }
    __syncthreads();

    for (int i = tid; i < CT * CC; i += 256) {
        int t = i / CC, c = i % CC;
        const float* w4 = &swt[c * 4];
        float acc = sbi[c];
        acc = fmaf(sx[(t + 0) * CC + c], w4[0], acc);
        acc = fmaf(sx[(t + 1) * CC + c], w4[1], acc);
        acc = fmaf(sx[(t + 2) * CC + c], w4[2], acc);
        acc = fmaf(sx[(t + 3) * CC + c], w4[3], acc);
        g_xbc[((size_t)(b * LEN + l0 + t)) * CD + c0 + c] = acc / (1.f + expf(-acc));
    }
}

// ---------------- scan phase 1: thread-per-p, h[16] in registers ------------
__global__ void __launch_bounds__(64)
k_scan1() {
    int c = blockIdx.x, hd = blockIdx.y, b = blockIdx.z;
    int p = threadIdx.x;
    __shared__ float sx[CH * HD];
    __shared__ __align__(16) float sB[CH * DS];
    __shared__ float sdt[CH];
    __shared__ float sdA[CH];
    int t0 = c * CH;
    size_t rb = ((size_t)(b * LEN + t0)) * CD;
    for (int idx = p; idx < CH * HD; idx += 64) {
        int t = idx >> 6, pp = idx & 63;
        sx[idx] = g_xbc[rb + (size_t)t * CD + hd * HD + pp];
    }
    for (int idx = p; idx < CH * DS; idx += 64) {
        int t = idx >> 4, n = idx & 15;
        sB[idx] = g_xbc[rb + (size_t)t * CD + DI + n];
    }
    {
        int tg = (b * LEN + t0 + p) * NH + hd;
        sdt[p] = g_dt[tg];
        sdA[p] = g_dA[tg];
    }
    __syncthreads();
    float h[16];
    #pragma unroll
    for (int n = 0; n < 16; n++) h[n] = 0.f;
    float run = 1.f;
    for (int t = 0; t < CH; t++) {
        float dA = sdA[t];
        float s = sdt[t] * sx[t * HD + p];
        run *= dA;
        #pragma unroll
        for (int n = 0; n < 16; n += 4) {
            float4 Bv = *(const float4*)&sB[t * DS + n];
            h[n]   = fmaf(dA, h[n],   s * Bv.x);
            h[n+1] = fmaf(dA, h[n+1], s * Bv.y);
            h[n+2] = fmaf(dA, h[n+2], s * Bv.z);
            h[n+3] = fmaf(dA, h[n+3], s * Bv.w);
        }
    }
    size_t base = ((size_t)((b * NH + hd) * NC + c)) * (HD * DS);
    #pragma unroll
    for (int n = 0; n < 16; n += 4)
        *(float4*)&g_hl[base + p * DS + n] = make_float4(h[n], h[n+1], h[n+2], h[n+3]);
    if (p == 0) g_P[(b * NH + hd) * NC + c] = run;
}

// ---------------- scan phase 2: prefix over chunks, 1 elem/thread -----------
__global__ void __launch_bounds__(256)
k_scan2() {
    int e = blockIdx.x * 256 + threadIdx.x;   // 0..1023
    int bh = blockIdx.y;                       // 0..47
    __shared__ float sP[NC];
    if (threadIdx.x < NC) sP[threadIdx.x] = g_P[bh * NC + threadIdx.x];
    __syncthreads();
    float H = 0.f;
    #pragma unroll 8
    for (int c = 0; c < NC; c++) {
        size_t base = ((size_t)(bh * NC + c)) * (HD * DS);
        g_hs[base + e] = H;
        H = fmaf(sP[c], H, g_hl[base + e]);
    }
}

// ---------------- scan phase 3: thread-per-p, emits gv = (y+Dx)*silu(z) -----
__global__ void __launch_bounds__(64)
k_scan3(const float* __restrict__ Dp) {
    int c = blockIdx.x, hd = blockIdx.y, b = blockIdx.z;
    int p = threadIdx.x;
    __shared__ float sx[CH * HD];
    __shared__ __align__(16) float sB[CH * DS];
    __shared__ __align__(16) float sC[CH * DS];
    __shared__ float sdt[CH];
    __shared__ float sdA[CH];
    int t0 = c * CH;
    size_t rb = ((size_t)(b * LEN + t0)) * CD;
    for (int idx = p; idx < CH * HD; idx += 64) {
        int t = idx >> 6, pp = idx & 63;
        sx[idx] = g_xbc[rb + (size_t)t * CD + hd * HD + pp];
    }
    for (int idx = p; idx < CH * DS; idx += 64) {
        int t = idx >> 4, n = idx & 15;
        sB[idx] = g_xbc[rb + (size_t)t * CD + DI + n];
        sC[idx] = g_xbc[rb + (size_t)t * CD + DI + DS + n];
    }
    {
        int tg = (b * LEN + t0 + p) * NH + hd;
        sdt[p] = g_dt[tg];
        sdA[p] = g_dA[tg];
    }
    __syncthreads();
    size_t base = ((size_t)((b * NH + hd) * NC + c)) * (HD * DS);
    float h[16];
    #pragma unroll
    for (int n = 0; n < 16; n += 4) {
        float4 v = *(const float4*)&g_hs[base + p * DS + n];
        h[n] = v.x; h[n+1] = v.y; h[n+2] = v.z; h[n+3] = v.w;
    }
    float Dh = Dp[hd];
    for (int t = 0; t < CH; t++) {
        float dA = sdA[t];
        float xv = sx[t * HD + p];
        float s = sdt[t] * xv;
        float y = 0.f;
        #pragma unroll
        for (int n = 0; n < 16; n += 4) {
            float4 Bv = *(const float4*)&sB[t * DS + n];
            float4 Cv = *(const float4*)&sC[t * DS + n];
            h[n]   = fmaf(dA, h[n],   s * Bv.x);
            h[n+1] = fmaf(dA, h[n+1], s * Bv.y);
            h[n+2] = fmaf(dA, h[n+2], s * Bv.z);
            h[n+3] = fmaf(dA, h[n+3], s * Bv.w);
            y += h[n]*Cv.x + h[n+1]*Cv.y + h[n+2]*Cv.z + h[n+3]*Cv.w;
        }
        size_t tok = (size_t)(b * LEN + t0 + t);
        float z = g_zx[tok * DP + hd * HD + p];
        float gv = (y + Dh * xv) * (z / (1.f + expf(-z)));
        g_y[tok * DI + hd * HD + p] = gv;
    }
}

// ---------------- RMS-norm over gv -> fp16 -----------------------------------
__global__ void k_rms(const float* __restrict__ gnw) {
    int row = blockIdx.x, tid = threadIdx.x;
    const float* gr = g_y + (size_t)row * DI;
    float gv[6];
    float sq = 0.f;
    #pragma unroll
    for (int i = 0; i < 6; i++) {
        int cc = tid + 256 * i;
        float g = gr[cc];
        gv[i] = g;
        sq += g * g;
    }
    __shared__ float sh[8];
    #pragma unroll
    for (int m = 16; m; m >>= 1) sq += __shfl_xor_sync(0xffffffffu, sq, m);
    if ((tid & 31) == 0) sh[tid >> 5] = sq;
    __syncthreads();
    if (tid < 32) {
        float a = (tid < 8) ? sh[tid] : 0.f;
        #pragma unroll
        for (int m = 4; m; m >>= 1) a += __shfl_xor_sync(0xffffffffu, a, m);
        if (tid == 0) sh[0] = a;
    }
    __syncthreads();
    float inv = rsqrtf(sh[0] * (1.f / DI) + 1e-5f);
    size_t base = (size_t)row * DI;
    #pragma unroll
    for (int i = 0; i < 6; i++) {
        int cc = tid + 256 * i;
        g_g16[base + cc] = __float2half_rn(gv[i] * inv * gnw[cc]);
    }
}

// ---------------- launcher ---------------------------------------------------
extern "C" void kernel_launch(void* const* d_in, const int* in_sizes, int n_in,
                              void* d_out, int out_size) {
    const float* x       = (const float*)d_in[0];
    const float* ln_w    = (const float*)d_in[1];
    const float* ln_b    = (const float*)d_in[2];
    const float* W_in    = (const float*)d_in[3];
    const float* conv_w  = (const float*)d_in[4];
    const float* conv_b  = (const float*)d_in[5];
    const float* dt_bias = (const float*)d_in[6];
    const float* A_log   = (const float*)d_in[7];
    const float* Dv      = (const float*)d_in[8];
    const float* gnw     = (const float*)d_in[9];
    const float* W_out   = (const float*)d_in[10];
    float* out = (float*)d_out;

    __half *pu, *pw1, *pg, *pw2;
    float *pzx;
    cudaGetSymbolAddress((void**)&pzx, g_zx);
    cudaGetSymbolAddress((void**)&pu,  g_u16);
    cudaGetSymbolAddress((void**)&pw1, g_W1);
    cudaGetSymbolAddress((void**)&pg,  g_g16);
    cudaGetSymbolAddress((void**)&pw2, g_W2);

    cudaFuncSetAttribute(k_gemm_h, cudaFuncAttributeMaxDynamicSharedMemorySize, GSMEM);

    k_cvt2<<<(W1PAD + W2N + 255)/256, 256>>>(W_in, W_out);
    k_ln<<<TT, 256>>>(x, ln_w, ln_b);
    k_gemm_h<<<dim3(NP1/128, TT/128), 256, GSMEM>>>(
        pu, pw1, pzx, nullptr, TT, DP, DM);
    k_dtda<<<(TT * NH + 255) / 256, 256>>>(dt_bias, A_log);
    k_conv<<<dim3(CD/CC, TT/CT), 256>>>(conv_w, conv_b);
    k_scan1<<<dim3(NC, NH, BSZ), 64>>>();
    k_scan2<<<dim3(4, BSZ * NH), 256>>>();
    k_scan3<<<dim3(NC, NH, BSZ), 64>>>(Dv);
    k_rms<<<TT, 256>>>(gnw);
    k_gemm_h<<<dim3(DM/128, TT/128), 256, GSMEM>>>(
        pg, pw2, out, x, TT, DM, DI);
}

// round 15
// speedup vs baseline: 1.5085x; 1.1509x over previous
#include <cuda_runtime.h>
#include <cuda_fp16.h>
#include <math.h>
#include <stdint.h>

#define BSZ 2
#define LEN 4096
#define TT (BSZ*LEN)          // 8192 tokens
#define DM 768
#define DI 1536
#define DS 16
#define NH 24
#define HD 64
#define CD 1568               // DI + 2*DS
#define DP 3128               // 2*DI + 2*DS + NH
#define NP1 3200              // DP padded to 128
#define NC 64                 // chunks
#define CH 64                 // chunk length (LEN/NC)

// ---------------- scratch (static device arrays; no runtime alloc) ----------
__device__ __align__(16) float g_zx[(size_t)TT*DP];
__device__ __align__(16) float g_xbc[(size_t)TT*CD];
__device__ float g_dt[TT*NH];
__device__ float g_dA[TT*NH];
__device__ __align__(16) float g_y[(size_t)TT*DI];
__device__ __align__(16) float g_hl[BSZ*NH*NC*HD*DS];
__device__ __align__(16) float g_hs[BSZ*NH*NC*HD*DS];
__device__ float g_P[BSZ*NH*NC];
// fp16 operand buffers (16B aligned for cp.async)
__device__ __align__(16) __half g_u16[(size_t)TT*DM];
__device__ __align__(16) __half g_W1[(size_t)NP1*DM];
__device__ __align__(16) __half g_g16[(size_t)TT*DI];
__device__ __align__(16) __half g_W2[(size_t)DM*DI];

// ---------------- packed f32x2 helpers (sm_103a FFMA2) ----------------------
typedef unsigned long long u64;
__device__ __forceinline__ u64 f2pk(float a, float b) {
    u64 r;
    asm("mov.b64 %0, {%1, %2};" : "=l"(r)
        : "r"(__float_as_uint(a)), "r"(__float_as_uint(b)));
    return r;
}
__device__ __forceinline__ u64 f2fma(u64 a, u64 b, u64 c) {
    u64 d;
    asm("fma.rn.f32x2 %0, %1, %2, %3;" : "=l"(d) : "l"(a), "l"(b), "l"(c));
    return d;
}
__device__ __forceinline__ u64 f2mul(u64 a, u64 b) {
    u64 d;
    asm("mul.rn.f32x2 %0, %1, %2;" : "=l"(d) : "l"(a), "l"(b));
    return d;
}
__device__ __forceinline__ float f2sum(u64 v) {
    unsigned lo, hi;
    asm("mov.b64 {%0, %1}, %2;" : "=r"(lo), "=r"(hi) : "l"(v));
    return __uint_as_float(lo) + __uint_as_float(hi);
}

__device__ __forceinline__ float fsigmoid(float v) {
    return 1.f / (1.f + __expf(-v));
}

// ---------------- weight convert (both weights, one launch) -----------------
#define W1PAD (NP1*DM)
#define W2N   (DM*DI)
__global__ void k_cvt2(const float* __restrict__ W1, const float* __restrict__ W2) {
    int i = blockIdx.x * 256 + threadIdx.x;
    if (i < W1PAD) {
        g_W1[i] = __float2half_rn((i < DP*DM) ? W1[i] : 0.f);
    } else if (i < W1PAD + W2N) {
        int j = i - W1PAD;
        g_W2[j] = __float2half_rn(W2[j]);
    }
}

// ---------------- layernorm -> fp16 ------------------------------------------
__global__ void k_ln(const float* __restrict__ x, const float* __restrict__ w,
                     const float* __restrict__ bb) {
    int row = blockIdx.x;
    int tid = threadIdx.x;
    const float* xr = x + (size_t)row * DM;
    float v0 = xr[tid], v1 = xr[tid + 256], v2 = xr[tid + 512];
    float s  = v0 + v1 + v2;
    float sq = v0*v0 + v1*v1 + v2*v2;
    __shared__ float sh[16];
    #pragma unroll
    for (int m = 16; m; m >>= 1) {
        s  += __shfl_xor_sync(0xffffffffu, s,  m);
        sq += __shfl_xor_sync(0xffffffffu, sq, m);
    }
    if ((tid & 31) == 0) { sh[tid >> 5] = s; sh[8 + (tid >> 5)] = sq; }
    __syncthreads();
    if (tid < 32) {
        float a  = (tid < 8) ? sh[tid]     : 0.f;
        float b2 = (tid < 8) ? sh[8 + tid] : 0.f;
        #pragma unroll
        for (int m = 4; m; m >>= 1) {
            a  += __shfl_xor_sync(0xffffffffu, a,  m);
            b2 += __shfl_xor_sync(0xffffffffu, b2, m);
        }
        if (tid == 0) { sh[0] = a; sh[8] = b2; }
    }
    __syncthreads();
    float mu  = sh[0] * (1.f / DM);
    float var = sh[8] * (1.f / DM) - mu * mu;
    float inv = rsqrtf(var + 1e-5f);
    size_t base = (size_t)row * DM;
    g_u16[base + tid]       = __float2half_rn((v0 - mu) * inv * w[tid]       + bb[tid]);
    g_u16[base + tid + 256] = __float2half_rn((v1 - mu) * inv * w[tid + 256] + bb[tid + 256]);
    g_u16[base + tid + 512] = __float2half_rn((v2 - mu) * inv * w[tid + 512] + bb[tid + 512]);
}

// ============================================================================
// fp16 single-pass HMMA NT GEMM: C[M,N] = A[M,K]*B[N,K]^T (+R).
// CTA tile 128x128x32, 8 warps (warp tile 64x32), 4-stage cp.async, ldmatrix.x4.
// ============================================================================
#define SP 40                     // smem row pitch in halves (32 data + 8 pad)
#define A_ELE (128*SP)
#define OFF_A 0
#define OFF_B (A_ELE*2)
#define STAGE_B (2*A_ELE*2)       // 20480 bytes
#define NSTG 4
#define GSMEM (NSTG*STAGE_B)      // 81920 bytes

__device__ __forceinline__ uint32_t smaddr(const void* p) {
    return (uint32_t)__cvta_generic_to_shared(p);
}
#define CPA(d, s) asm volatile("cp.async.cg.shared.global [%0], [%1], 16;\n" :: "r"(d), "l"(s))
#define CPCOMMIT() asm volatile("cp.async.commit_group;\n")
#define CPWAIT2() asm volatile("cp.async.wait_group 2;\n")
#define LDSM4(r0,r1,r2,r3,a) asm volatile( \
    "ldmatrix.sync.aligned.m8n8.x4.shared.b16 {%0,%1,%2,%3}, [%4];\n" \
    : "=r"(r0),"=r"(r1),"=r"(r2),"=r"(r3) : "r"(a))
#define MMAH(d, a, b0, b1) \
  asm volatile("mma.sync.aligned.m16n8k16.row.col.f32.f16.f16.f32 " \
      "{%0,%1,%2,%3}, {%4,%5,%6,%7}, {%8,%9}, {%0,%1,%2,%3};\n" \
      : "+f"(d[0]), "+f"(d[1]), "+f"(d[2]), "+f"(d[3]) \
      : "r"(a[0]), "r"(a[1]), "r"(a[2]), "r"(a[3]), "r"(b0), "r"(b1))

__global__ void __launch_bounds__(256, 2)
k_gemm_h(const __half* __restrict__ A, const __half* __restrict__ B,
         float* __restrict__ C, const float* __restrict__ R,
         int M, int N, int K) {
    extern __shared__ __half sm[];
    const int tid = threadIdx.x;
    const int warp = tid >> 5, lane = tid & 31;
    const int wm = (warp & 1) * 64;
    const int wn = (warp >> 1) * 32;
    const int bm = blockIdx.y * 128, bn = blockIdx.x * 128;
    const int nIter = K >> 5;
    const uint32_t smb = smaddr(sm);

    const int a_r = lane & 15, a_k = (lane >> 4) << 3;
    const int b_r = (lane & 7) + ((lane >> 4) << 3);
    const int b_k = ((lane >> 3) & 1) << 3;

    float acc[4][4][4];
    #pragma unroll
    for (int i = 0; i < 4; i++)
        #pragma unroll
        for (int j = 0; j < 4; j++)
            #pragma unroll
            for (int k = 0; k < 4; k++) acc[i][j][k] = 0.f;

    #define ISSUE(kt) do {                                                     \
        int _b = (kt) & (NSTG - 1), _k = (kt) << 5;                            \
        uint32_t _sb = smb + (uint32_t)_b * STAGE_B;                           \
        _Pragma("unroll")                                                      \
        for (int _i = 0; _i < 2; _i++) {                                       \
            int _idx = tid + 256 * _i;                                         \
            int _r = _idx >> 2, _c = (_idx & 3) << 3;                          \
            uint32_t _d = (uint32_t)(_r * SP + _c) * 2;                        \
            CPA(_sb + OFF_A + _d, A + (size_t)(bm + _r) * K + _k + _c);        \
            CPA(_sb + OFF_B + _d, B + (size_t)(bn + _r) * K + _k + _c);        \
        }                                                                      \
        CPCOMMIT();                                                            \
    } while (0)

    ISSUE(0);
    ISSUE(1);
    ISSUE(2);

    for (int kt = 0; kt < nIter; kt++) {
        CPWAIT2();
        __syncthreads();
        const int s = kt & (NSTG - 1);
        const uint32_t sb = smb + (uint32_t)s * STAGE_B;

        #pragma unroll
        for (int sub = 0; sub < 32; sub += 16) {
            unsigned bh[2][4];
            #pragma unroll
            for (int p = 0; p < 2; p++) {
                uint32_t ba = sb + OFF_B +
                    (uint32_t)((wn + p*16 + b_r) * SP + sub + b_k) * 2;
                LDSM4(bh[p][0], bh[p][1], bh[p][2], bh[p][3], ba);
            }
            #pragma unroll
            for (int mt = 0; mt < 4; mt++) {
                unsigned ah[4];
                uint32_t aa = sb + OFF_A +
                    (uint32_t)((wm + mt*16 + a_r) * SP + sub + a_k) * 2;
                LDSM4(ah[0], ah[1], ah[2], ah[3], aa);
                #pragma unroll
                for (int p = 0; p < 2; p++) {
                    MMAH(acc[mt][2*p],   ah, bh[p][0], bh[p][1]);
                    MMAH(acc[mt][2*p+1], ah, bh[p][2], bh[p][3]);
                }
            }
        }

        int nk = kt + 3;
        if (nk < nIter) { ISSUE(nk); }
        else            { CPCOMMIT(); }
    }

    const int g = lane >> 2, q = lane & 3;
    #pragma unroll
    for (int mt = 0; mt < 4; mt++) {
        int row0 = bm + wm + mt * 16 + g;
        #pragma unroll
        for (int nt = 0; nt < 4; nt++) {
            int col = bn + wn + nt * 8 + 2 * q;
            if (col < N) {
                float2 v0, v1;
                v0.x = acc[mt][nt][0]; v0.y = acc[mt][nt][1];
                v1.x = acc[mt][nt][2]; v1.y = acc[mt][nt][3];
                if (R) {
                    const float* rr0 = R + (size_t)row0 * N + col;
                    const float* rr1 = R + (size_t)(row0 + 8) * N + col;
                    v0.x += rr0[0]; v0.y += rr0[1];
                    v1.x += rr1[0]; v1.y += rr1[1];
                }
                *(float2*)(C + (size_t)row0 * N + col) = v0;
                *(float2*)(C + (size_t)(row0 + 8) * N + col) = v1;
            }
        }
    }
    #undef ISSUE
}

// ---------------- dt = softplus(raw + bias), dA = exp(dt * -exp(A_log)) -----
__global__ void k_dtda(const float* __restrict__ dtb, const float* __restrict__ alog) {
    int i = blockIdx.x * 256 + threadIdx.x;
    if (i >= TT * NH) return;
    int h = i % NH, t = i / NH;
    float xv = g_zx[(size_t)t * DP + (DI + CD) + h] + dtb[h];
    float dt = (xv > 20.f) ? xv : __logf(1.f + __expf(xv));
    float A = -__expf(alog[h]);
    g_dt[i] = dt;
    g_dA[i] = __expf(dt * A);
}

// ---------------- causal depthwise conv(4): smem-tiled -----------------------
#define CT 32
#define CC 224
__global__ void __launch_bounds__(256)
k_conv(const float* __restrict__ cw, const float* __restrict__ cb) {
    __shared__ float sx[(CT + 3) * CC];
    __shared__ float swt[CC * 4];
    __shared__ float sbi[CC];
    int c0 = blockIdx.x * CC;
    int tblk = blockIdx.y;
    int b = (tblk * CT) / LEN;
    int l0 = (tblk * CT) % LEN;
    int tid = threadIdx.x;

    for (int i = tid; i < CC * 4; i += 256) swt[i] = cw[c0 * 4 + i];
    for (int i = tid; i < CC; i += 256)     sbi[i] = cb[c0 + i];
    for (int i = tid; i < (CT + 3) * CC; i += 256) {
        int r = i / CC, c = i % CC;
        int l = l0 - 3 + r;
        sx[i] = (l >= 0) ? g_zx[((size_t)(b * LEN + l)) * DP + DI + c0 + c] : 0.f;
    }
    __syncthreads();

    for (int i = tid; i < CT * CC; i += 256) {
        int t = i / CC, c = i % CC;
        const float* w4 = &swt[c * 4];
        float acc = sbi[c];
        acc = fmaf(sx[(t + 0) * CC + c], w4[0], acc);
        acc = fmaf(sx[(t + 1) * CC + c], w4[1], acc);
        acc = fmaf(sx[(t + 2) * CC + c], w4[2], acc);
        acc = fmaf(sx[(t + 3) * CC + c], w4[3], acc);
        g_xbc[((size_t)(b * LEN + l0 + t)) * CD + c0 + c] = acc * fsigmoid(acc);
    }
}

// ---------------- scan phase 1: thread-per-p, packed f32x2 h-update ----------
__global__ void __launch_bounds__(64)
k_scan1() {
    int c = blockIdx.x, hd = blockIdx.y, b = blockIdx.z;
    int p = threadIdx.x;
    __shared__ float sx[CH * HD];
    __shared__ __align__(16) float sB[CH * DS];
    __shared__ float sdt[CH];
    __shared__ float sdA[CH];
    int t0 = c * CH;
    size_t rb = ((size_t)(b * LEN + t0)) * CD;
    for (int idx = p; idx < CH * HD; idx += 64) {
        int t = idx >> 6, pp = idx & 63;
        sx[idx] = g_xbc[rb + (size_t)t * CD + hd * HD + pp];
    }
    for (int idx = p; idx < CH * DS; idx += 64) {
        int t = idx >> 4, n = idx & 15;
        sB[idx] = g_xbc[rb + (size_t)t * CD + DI + n];
    }
    {
        int tg = (b * LEN + t0 + p) * NH + hd;
        sdt[p] = g_dt[tg];
        sdA[p] = g_dA[tg];
    }
    __syncthreads();
    u64 h2[8];
    #pragma unroll
    for (int n = 0; n < 8; n++) h2[n] = 0ull;
    float run = 1.f;
    for (int t = 0; t < CH; t++) {
        float dA = sdA[t];
        float s = sdt[t] * sx[t * HD + p];
        run *= dA;
        u64 dA2 = f2pk(dA, dA), s2 = f2pk(s, s);
        #pragma unroll
        for (int n = 0; n < 4; n++) {
            ulonglong2 Bq = *(const ulonglong2*)&sB[t * DS + n * 4];
            h2[2*n]   = f2fma(dA2, h2[2*n],   f2mul(s2, Bq.x));
            h2[2*n+1] = f2fma(dA2, h2[2*n+1], f2mul(s2, Bq.y));
        }
    }
    size_t base = ((size_t)((b * NH + hd) * NC + c)) * (HD * DS);
    #pragma unroll
    for (int n = 0; n < 4; n++) {
        ulonglong2 v; v.x = h2[2*n]; v.y = h2[2*n+1];
        *(ulonglong2*)&g_hl[base + p * DS + n * 4] = v;
    }
    if (p == 0) g_P[(b * NH + hd) * NC + c] = run;
}

// ---------------- scan phase 2: prefix over chunks, 1 elem/thread -----------
__global__ void __launch_bounds__(256)
k_scan2() {
    int e = blockIdx.x * 256 + threadIdx.x;   // 0..1023
    int bh = blockIdx.y;                       // 0..47
    __shared__ float sP[NC];
    if (threadIdx.x < NC) sP[threadIdx.x] = g_P[bh * NC + threadIdx.x];
    __syncthreads();
    float H = 0.f;
    #pragma unroll 8
    for (int c = 0; c < NC; c++) {
        size_t base = ((size_t)(bh * NC + c)) * (HD * DS);
        g_hs[base + e] = H;
        H = fmaf(sP[c], H, g_hl[base + e]);
    }
}

// ---------------- scan phase 3: thread-per-p, packed f32x2, emits y ----------
__global__ void __launch_bounds__(64)
k_scan3(const float* __restrict__ Dp) {
    int c = blockIdx.x, hd = blockIdx.y, b = blockIdx.z;
    int p = threadIdx.x;
    __shared__ float sx[CH * HD];
    __shared__ __align__(16) float sB[CH * DS];
    __shared__ __align__(16) float sC[CH * DS];
    __shared__ float sdt[CH];
    __shared__ float sdA[CH];
    int t0 = c * CH;
    size_t rb = ((size_t)(b * LEN + t0)) * CD;
    for (int idx = p; idx < CH * HD; idx += 64) {
        int t = idx >> 6, pp = idx & 63;
        sx[idx] = g_xbc[rb + (size_t)t * CD + hd * HD + pp];
    }
    for (int idx = p; idx < CH * DS; idx += 64) {
        int t = idx >> 4, n = idx & 15;
        sB[idx] = g_xbc[rb + (size_t)t * CD + DI + n];
        sC[idx] = g_xbc[rb + (size_t)t * CD + DI + DS + n];
    }
    {
        int tg = (b * LEN + t0 + p) * NH + hd;
        sdt[p] = g_dt[tg];
        sdA[p] = g_dA[tg];
    }
    __syncthreads();
    size_t base = ((size_t)((b * NH + hd) * NC + c)) * (HD * DS);
    u64 h2[8];
    #pragma unroll
    for (int n = 0; n < 4; n++) {
        ulonglong2 v = *(const ulonglong2*)&g_hs[base + p * DS + n * 4];
        h2[2*n] = v.x; h2[2*n+1] = v.y;
    }
    float Dh = Dp[hd];
    for (int t = 0; t < CH; t++) {
        float dA = sdA[t];
        float xv = sx[t * HD + p];
        float s = sdt[t] * xv;
        u64 dA2 = f2pk(dA, dA), s2 = f2pk(s, s);
        u64 y2 = 0ull;
        #pragma unroll
        for (int n = 0; n < 4; n++) {
            ulonglong2 Bq = *(const ulonglong2*)&sB[t * DS + n * 4];
            ulonglong2 Cq = *(const ulonglong2*)&sC[t * DS + n * 4];
            h2[2*n]   = f2fma(dA2, h2[2*n],   f2mul(s2, Bq.x));
            h2[2*n+1] = f2fma(dA2, h2[2*n+1], f2mul(s2, Bq.y));
            y2 = f2fma(h2[2*n],   Cq.x, y2);
            y2 = f2fma(h2[2*n+1], Cq.y, y2);
        }
        float y = f2sum(y2);
        g_y[((size_t)(b * LEN + t0 + t)) * DI + hd * HD + p] = y + Dh * xv;
    }
}

// ---------------- gating + RMSNorm -> fp16 -----------------------------------
__global__ void k_gate(const float* __restrict__ gnw) {
    int row = blockIdx.x, tid = threadIdx.x;
    const float* yr = g_y  + (size_t)row * DI;
    const float* zr = g_zx + (size_t)row * DP;
    float gv[6];
    float sq = 0.f;
    #pragma unroll
    for (int i = 0; i < 6; i++) {
        int cc = tid + 256 * i;
        float z = zr[cc];
        float g = yr[cc] * (z * fsigmoid(z));
        gv[i] = g;
        sq += g * g;
    }
    __shared__ float sh[8];
    #pragma unroll
    for (int m = 16; m; m >>= 1) sq += __shfl_xor_sync(0xffffffffu, sq, m);
    if ((tid & 31) == 0) sh[tid >> 5] = sq;
    __syncthreads();
    if (tid < 32) {
        float a = (tid < 8) ? sh[tid] : 0.f;
        #pragma unroll
        for (int m = 4; m; m >>= 1) a += __shfl_xor_sync(0xffffffffu, a, m);
        if (tid == 0) sh[0] = a;
    }
    __syncthreads();
    float inv = rsqrtf(sh[0] * (1.f / DI) + 1e-5f);
    size_t base = (size_t)row * DI;
    #pragma unroll
    for (int i = 0; i < 6; i++) {
        int cc = tid + 256 * i;
        g_g16[base + cc] = __float2half_rn(gv[i] * inv * gnw[cc]);
    }
}

// ---------------- launcher ---------------------------------------------------
extern "C" void kernel_launch(void* const* d_in, const int* in_sizes, int n_in,
                              void* d_out, int out_size) {
    const float* x       = (const float*)d_in[0];
    const float* ln_w    = (const float*)d_in[1];
    const float* ln_b    = (const float*)d_in[2];
    const float* W_in    = (const float*)d_in[3];
    const float* conv_w  = (const float*)d_in[4];
    const float* conv_b  = (const float*)d_in[5];
    const float* dt_bias = (const float*)d_in[6];
    const float* A_log   = (const float*)d_in[7];
    const float* Dv      = (const float*)d_in[8];
    const float* gnw     = (const float*)d_in[9];
    const float* W_out   = (const float*)d_in[10];
    float* out = (float*)d_out;

    __half *pu, *pw1, *pg, *pw2;
    float *pzx;
    cudaGetSymbolAddress((void**)&pzx, g_zx);
    cudaGetSymbolAddress((void**)&pu,  g_u16);
    cudaGetSymbolAddress((void**)&pw1, g_W1);
    cudaGetSymbolAddress((void**)&pg,  g_g16);
    cudaGetSymbolAddress((void**)&pw2, g_W2);

    cudaFuncSetAttribute(k_gemm_h, cudaFuncAttributeMaxDynamicSharedMemorySize, GSMEM);

    k_cvt2<<<(W1PAD + W2N + 255)/256, 256>>>(W_in, W_out);
    k_ln<<<TT, 256>>>(x, ln_w, ln_b);
    k_gemm_h<<<dim3(NP1/128, TT/128), 256, GSMEM>>>(
        pu, pw1, pzx, nullptr, TT, DP, DM);
    k_dtda<<<(TT * NH + 255) / 256, 256>>>(dt_bias, A_log);
    k_conv<<<dim3(CD/CC, TT/CT), 256>>>(conv_w, conv_b);
    k_scan1<<<dim3(NC, NH, BSZ), 64>>>();
    k_scan2<<<dim3(4, BSZ * NH), 256>>>();
    k_scan3<<<dim3(NC, NH, BSZ), 64>>>(Dv);
    k_gate<<<TT, 256>>>(gnw);
    k_gemm_h<<<dim3(DM/128, TT/128), 256, GSMEM>>>(
        pg, pw2, out, x, TT, DM, DI);
}

// round 16
// speedup vs baseline: 1.5705x; 1.0411x over previous
#include <cuda_runtime.h>
#include <cuda_fp16.h>
#include <math.h>
#include <stdint.h>

#define BSZ 2
#define LEN 4096
#define TT (BSZ*LEN)          // 8192 tokens
#define DM 768
#define DI 1536
#define DS 16
#define NH 24
#define HD 64
#define CD 1568               // DI + 2*DS
#define DP 3128               // 2*DI + 2*DS + NH
#define NP1 3200              // DP padded to 128
#define NC 64                 // chunks
#define CH 64                 // chunk length (LEN/NC)

// ---------------- scratch (static device arrays; no runtime alloc) ----------
__device__ __align__(16) float g_zx[(size_t)TT*DP];
__device__ __align__(16) float g_xbc[(size_t)TT*CD];
__device__ float g_dt[TT*NH];
__device__ float g_dA[TT*NH];
__device__ __align__(16) float g_y[(size_t)TT*DI];
__device__ __align__(16) float g_hl[BSZ*NH*NC*HD*DS];
__device__ __align__(16) float g_hs[BSZ*NH*NC*HD*DS];
__device__ float g_P[BSZ*NH*NC];
// fp16 operand buffers (16B aligned for cp.async)
__device__ __align__(16) __half g_u16[(size_t)TT*DM];
__device__ __align__(16) __half g_W1[(size_t)NP1*DM];
__device__ __align__(16) __half g_g16[(size_t)TT*DI];
__device__ __align__(16) __half g_W2[(size_t)DM*DI];

// ---------------- packed f32x2 helpers (sm_103a FFMA2) ----------------------
typedef unsigned long long u64;
__device__ __forceinline__ u64 f2pk(float a, float b) {
    u64 r;
    asm("mov.b64 %0, {%1, %2};" : "=l"(r)
        : "r"(__float_as_uint(a)), "r"(__float_as_uint(b)));
    return r;
}
__device__ __forceinline__ u64 f2fma(u64 a, u64 b, u64 c) {
    u64 d;
    asm("fma.rn.f32x2 %0, %1, %2, %3;" : "=l"(d) : "l"(a), "l"(b), "l"(c));
    return d;
}
__device__ __forceinline__ u64 f2mul(u64 a, u64 b) {
    u64 d;
    asm("mul.rn.f32x2 %0, %1, %2;" : "=l"(d) : "l"(a), "l"(b));
    return d;
}
__device__ __forceinline__ u64 f2add(u64 a, u64 b) {
    u64 d;
    asm("add.rn.f32x2 %0, %1, %2;" : "=l"(d) : "l"(a), "l"(b));
    return d;
}
__device__ __forceinline__ float f2sum(u64 v) {
    unsigned lo, hi;
    asm("mov.b64 {%0, %1}, %2;" : "=r"(lo), "=r"(hi) : "l"(v));
    return __uint_as_float(lo) + __uint_as_float(hi);
}

__device__ __forceinline__ float fsigmoid(float v) {
    return 1.f / (1.f + __expf(-v));
}

// ---------------- weight convert (both weights, one launch) -----------------
#define W1PAD (NP1*DM)
#define W2N   (DM*DI)
__global__ void k_cvt2(const float* __restrict__ W1, const float* __restrict__ W2) {
    int i = blockIdx.x * 256 + threadIdx.x;
    if (i < W1PAD) {
        g_W1[i] = __float2half_rn((i < DP*DM) ? W1[i] : 0.f);
    } else if (i < W1PAD + W2N) {
        int j = i - W1PAD;
        g_W2[j] = __float2half_rn(W2[j]);
    }
}

// ---------------- layernorm -> fp16 ------------------------------------------
__global__ void k_ln(const float* __restrict__ x, const float* __restrict__ w,
                     const float* __restrict__ bb) {
    int row = blockIdx.x;
    int tid = threadIdx.x;
    const float* xr = x + (size_t)row * DM;
    float v0 = xr[tid], v1 = xr[tid + 256], v2 = xr[tid + 512];
    float s  = v0 + v1 + v2;
    float sq = v0*v0 + v1*v1 + v2*v2;
    __shared__ float sh[16];
    #pragma unroll
    for (int m = 16; m; m >>= 1) {
        s  += __shfl_xor_sync(0xffffffffu, s,  m);
        sq += __shfl_xor_sync(0xffffffffu, sq, m);
    }
    if ((tid & 31) == 0) { sh[tid >> 5] = s; sh[8 + (tid >> 5)] = sq; }
    __syncthreads();
    if (tid < 32) {
        float a  = (tid < 8) ? sh[tid]     : 0.f;
        float b2 = (tid < 8) ? sh[8 + tid] : 0.f;
        #pragma unroll
        for (int m = 4; m; m >>= 1) {
            a  += __shfl_xor_sync(0xffffffffu, a,  m);
            b2 += __shfl_xor_sync(0xffffffffu, b2, m);
        }
        if (tid == 0) { sh[0] = a; sh[8] = b2; }
    }
    __syncthreads();
    float mu  = sh[0] * (1.f / DM);
    float var = sh[8] * (1.f / DM) - mu * mu;
    float inv = rsqrtf(var + 1e-5f);
    size_t base = (size_t)row * DM;
    g_u16[base + tid]       = __float2half_rn((v0 - mu) * inv * w[tid]       + bb[tid]);
    g_u16[base + tid + 256] = __float2half_rn((v1 - mu) * inv * w[tid + 256] + bb[tid + 256]);
    g_u16[base + tid + 512] = __float2half_rn((v2 - mu) * inv * w[tid + 512] + bb[tid + 512]);
}

// ============================================================================
// fp16 single-pass HMMA NT GEMM: C[M,N] = A[M,K]*B[N,K]^T (+R).
// CTA tile 128x128x32, 8 warps (warp tile 64x32), 4-stage cp.async, ldmatrix.x4.
// ============================================================================
#define SP 40                     // smem row pitch in halves (32 data + 8 pad)
#define A_ELE (128*SP)
#define OFF_A 0
#define OFF_B (A_ELE*2)
#define STAGE_B (2*A_ELE*2)       // 20480 bytes
#define NSTG 4
#define GSMEM (NSTG*STAGE_B)      // 81920 bytes

__device__ __forceinline__ uint32_t smaddr(const void* p) {
    return (uint32_t)__cvta_generic_to_shared(p);
}
#define CPA(d, s) asm volatile("cp.async.cg.shared.global [%0], [%1], 16;\n" :: "r"(d), "l"(s))
#define CPCOMMIT() asm volatile("cp.async.commit_group;\n")
#define CPWAIT2() asm volatile("cp.async.wait_group 2;\n")
#define LDSM4(r0,r1,r2,r3,a) asm volatile( \
    "ldmatrix.sync.aligned.m8n8.x4.shared.b16 {%0,%1,%2,%3}, [%4];\n" \
    : "=r"(r0),"=r"(r1),"=r"(r2),"=r"(r3) : "r"(a))
#define MMAH(d, a, b0, b1) \
  asm volatile("mma.sync.aligned.m16n8k16.row.col.f32.f16.f16.f32 " \
      "{%0,%1,%2,%3}, {%4,%5,%6,%7}, {%8,%9}, {%0,%1,%2,%3};\n" \
      : "+f"(d[0]), "+f"(d[1]), "+f"(d[2]), "+f"(d[3]) \
      : "r"(a[0]), "r"(a[1]), "r"(a[2]), "r"(a[3]), "r"(b0), "r"(b1))

__global__ void __launch_bounds__(256, 2)
k_gemm_h(const __half* __restrict__ A, const __half* __restrict__ B,
         float* __restrict__ C, const float* __restrict__ R,
         int M, int N, int K) {
    extern __shared__ __half sm[];
    const int tid = threadIdx.x;
    const int warp = tid >> 5, lane = tid & 31;
    const int wm = (warp & 1) * 64;
    const int wn = (warp >> 1) * 32;
    const int bm = blockIdx.y * 128, bn = blockIdx.x * 128;
    const int nIter = K >> 5;
    const uint32_t smb = smaddr(sm);

    const int a_r = lane & 15, a_k = (lane >> 4) << 3;
    const int b_r = (lane & 7) + ((lane >> 4) << 3);
    const int b_k = ((lane >> 3) & 1) << 3;

    float acc[4][4][4];
    #pragma unroll
    for (int i = 0; i < 4; i++)
        #pragma unroll
        for (int j = 0; j < 4; j++)
            #pragma unroll
            for (int k = 0; k < 4; k++) acc[i][j][k] = 0.f;

    #define ISSUE(kt) do {                                                     \
        int _b = (kt) & (NSTG - 1), _k = (kt) << 5;                            \
        uint32_t _sb = smb + (uint32_t)_b * STAGE_B;                           \
        _Pragma("unroll")                                                      \
        for (int _i = 0; _i < 2; _i++) {                                       \
            int _idx = tid + 256 * _i;                                         \
            int _r = _idx >> 2, _c = (_idx & 3) << 3;                          \
            uint32_t _d = (uint32_t)(_r * SP + _c) * 2;                        \
            CPA(_sb + OFF_A + _d, A + (size_t)(bm + _r) * K + _k + _c);        \
            CPA(_sb + OFF_B + _d, B + (size_t)(bn + _r) * K + _k + _c);        \
        }                                                                      \
        CPCOMMIT();                                                            \
    } while (0)

    ISSUE(0);
    ISSUE(1);
    ISSUE(2);

    for (int kt = 0; kt < nIter; kt++) {
        CPWAIT2();
        __syncthreads();
        const int s = kt & (NSTG - 1);
        const uint32_t sb = smb + (uint32_t)s * STAGE_B;

        #pragma unroll
        for (int sub = 0; sub < 32; sub += 16) {
            unsigned bh[2][4];
            #pragma unroll
            for (int p = 0; p < 2; p++) {
                uint32_t ba = sb + OFF_B +
                    (uint32_t)((wn + p*16 + b_r) * SP + sub + b_k) * 2;
                LDSM4(bh[p][0], bh[p][1], bh[p][2], bh[p][3], ba);
            }
            #pragma unroll
            for (int mt = 0; mt < 4; mt++) {
                unsigned ah[4];
                uint32_t aa = sb + OFF_A +
                    (uint32_t)((wm + mt*16 + a_r) * SP + sub + a_k) * 2;
                LDSM4(ah[0], ah[1], ah[2], ah[3], aa);
                #pragma unroll
                for (int p = 0; p < 2; p++) {
                    MMAH(acc[mt][2*p],   ah, bh[p][0], bh[p][1]);
                    MMAH(acc[mt][2*p+1], ah, bh[p][2], bh[p][3]);
                }
            }
        }

        int nk = kt + 3;
        if (nk < nIter) { ISSUE(nk); }
        else            { CPCOMMIT(); }
    }

    const int g = lane >> 2, q = lane & 3;
    #pragma unroll
    for (int mt = 0; mt < 4; mt++) {
        int row0 = bm + wm + mt * 16 + g;
        #pragma unroll
        for (int nt = 0; nt < 4; nt++) {
            int col = bn + wn + nt * 8 + 2 * q;
            if (col < N) {
                float2 v0, v1;
                v0.x = acc[mt][nt][0]; v0.y = acc[mt][nt][1];
                v1.x = acc[mt][nt][2]; v1.y = acc[mt][nt][3];
                if (R) {
                    const float* rr0 = R + (size_t)row0 * N + col;
                    const float* rr1 = R + (size_t)(row0 + 8) * N + col;
                    v0.x += rr0[0]; v0.y += rr0[1];
                    v1.x += rr1[0]; v1.y += rr1[1];
                }
                *(float2*)(C + (size_t)row0 * N + col) = v0;
                *(float2*)(C + (size_t)(row0 + 8) * N + col) = v1;
            }
        }
    }
    #undef ISSUE
}

// ---------------- dt = softplus(raw + bias), dA = exp(dt * -exp(A_log)) -----
__global__ void k_dtda(const float* __restrict__ dtb, const float* __restrict__ alog) {
    int i = blockIdx.x * 256 + threadIdx.x;
    if (i >= TT * NH) return;
    int h = i % NH, t = i / NH;
    float xv = g_zx[(size_t)t * DP + (DI + CD) + h] + dtb[h];
    float dt = (xv > 20.f) ? xv : __logf(1.f + __expf(xv));
    float A = -__expf(alog[h]);
    g_dt[i] = dt;
    g_dA[i] = __expf(dt * A);
}

// ---------------- causal depthwise conv(4): smem-tiled -----------------------
#define CT 32
#define CC 224
__global__ void __launch_bounds__(256)
k_conv(const float* __restrict__ cw, const float* __restrict__ cb) {
    __shared__ float sx[(CT + 3) * CC];
    __shared__ float swt[CC * 4];
    __shared__ float sbi[CC];
    int c0 = blockIdx.x * CC;
    int tblk = blockIdx.y;
    int b = (tblk * CT) / LEN;
    int l0 = (tblk * CT) % LEN;
    int tid = threadIdx.x;

    for (int i = tid; i < CC * 4; i += 256) swt[i] = cw[c0 * 4 + i];
    for (int i = tid; i < CC; i += 256)     sbi[i] = cb[c0 + i];
    for (int i = tid; i < (CT + 3) * CC; i += 256) {
        int r = i / CC, c = i % CC;
        int l = l0 - 3 + r;
        sx[i] = (l >= 0) ? g_zx[((size_t)(b * LEN + l)) * DP + DI + c0 + c] : 0.f;
    }
    __syncthreads();

    for (int i = tid; i < CT * CC; i += 256) {
        int t = i / CC, c = i % CC;
        const float* w4 = &swt[c * 4];
        float acc = sbi[c];
        acc = fmaf(sx[(t + 0) * CC + c], w4[0], acc);
        acc = fmaf(sx[(t + 1) * CC + c], w4[1], acc);
        acc = fmaf(sx[(t + 2) * CC + c], w4[2], acc);
        acc = fmaf(sx[(t + 3) * CC + c], w4[3], acc);
        g_xbc[((size_t)(b * LEN + l0 + t)) * CD + c0 + c] = acc * fsigmoid(acc);
    }
}

// ---------------- scan phase 1: thread-per-p, fp16 x tile, packed f32x2 -----
__global__ void __launch_bounds__(64)
k_scan1() {
    int c = blockIdx.x, hd = blockIdx.y, b = blockIdx.z;
    int p = threadIdx.x;
    __shared__ __half sx16[CH * HD];
    __shared__ __align__(16) float sB[CH * DS];
    __shared__ float sdt[CH];
    __shared__ float sdA[CH];
    int t0 = c * CH;
    size_t rb = ((size_t)(b * LEN + t0)) * CD;
    for (int idx = p; idx < CH * HD; idx += 64) {
        int t = idx >> 6, pp = idx & 63;
        sx16[idx] = __float2half_rn(g_xbc[rb + (size_t)t * CD + hd * HD + pp]);
    }
    for (int idx = p; idx < CH * DS; idx += 64) {
        int t = idx >> 4, n = idx & 15;
        sB[idx] = g_xbc[rb + (size_t)t * CD + DI + n];
    }
    {
        int tg = (b * LEN + t0 + p) * NH + hd;
        sdt[p] = g_dt[tg];
        sdA[p] = g_dA[tg];
    }
    __syncthreads();
    u64 h2[8];
    #pragma unroll
    for (int n = 0; n < 8; n++) h2[n] = 0ull;
    float run = 1.f;
    for (int t = 0; t < CH; t++) {
        float dA = sdA[t];
        float s = sdt[t] * __half2float(sx16[t * HD + p]);
        run *= dA;
        u64 dA2 = f2pk(dA, dA), s2 = f2pk(s, s);
        #pragma unroll
        for (int n = 0; n < 4; n++) {
            ulonglong2 Bq = *(const ulonglong2*)&sB[t * DS + n * 4];
            h2[2*n]   = f2fma(dA2, h2[2*n],   f2mul(s2, Bq.x));
            h2[2*n+1] = f2fma(dA2, h2[2*n+1], f2mul(s2, Bq.y));
        }
    }
    size_t base = ((size_t)((b * NH + hd) * NC + c)) * (HD * DS);
    #pragma unroll
    for (int n = 0; n < 4; n++) {
        ulonglong2 v; v.x = h2[2*n]; v.y = h2[2*n+1];
        *(ulonglong2*)&g_hl[base + p * DS + n * 4] = v;
    }
    if (p == 0) g_P[(b * NH + hd) * NC + c] = run;
}

// ---------------- scan phase 2: prefix over chunks, 1 elem/thread -----------
__global__ void __launch_bounds__(256)
k_scan2() {
    int e = blockIdx.x * 256 + threadIdx.x;   // 0..1023
    int bh = blockIdx.y;                       // 0..47
    __shared__ float sP[NC];
    if (threadIdx.x < NC) sP[threadIdx.x] = g_P[bh * NC + threadIdx.x];
    __syncthreads();
    float H = 0.f;
    #pragma unroll 8
    for (int c = 0; c < NC; c++) {
        size_t base = ((size_t)(bh * NC + c)) * (HD * DS);
        g_hs[base + e] = H;
        H = fmaf(sP[c], H, g_hl[base + e]);
    }
}

// ---------------- scan phase 3: fp16 x tile, dual y chains, emits y ----------
__global__ void __launch_bounds__(64)
k_scan3(const float* __restrict__ Dp) {
    int c = blockIdx.x, hd = blockIdx.y, b = blockIdx.z;
    int p = threadIdx.x;
    __shared__ __half sx16[CH * HD];
    __shared__ __align__(16) float sB[CH * DS];
    __shared__ __align__(16) float sC[CH * DS];
    __shared__ float sdt[CH];
    __shared__ float sdA[CH];
    int t0 = c * CH;
    size_t rb = ((size_t)(b * LEN + t0)) * CD;
    for (int idx = p; idx < CH * HD; idx += 64) {
        int t = idx >> 6, pp = idx & 63;
        sx16[idx] = __float2half_rn(g_xbc[rb + (size_t)t * CD + hd * HD + pp]);
    }
    for (int idx = p; idx < CH * DS; idx += 64) {
        int t = idx >> 4, n = idx & 15;
        sB[idx] = g_xbc[rb + (size_t)t * CD + DI + n];
        sC[idx] = g_xbc[rb + (size_t)t * CD + DI + DS + n];
    }
    {
        int tg = (b * LEN + t0 + p) * NH + hd;
        sdt[p] = g_dt[tg];
        sdA[p] = g_dA[tg];
    }
    __syncthreads();
    size_t base = ((size_t)((b * NH + hd) * NC + c)) * (HD * DS);
    u64 h2[8];
    #pragma unroll
    for (int n = 0; n < 4; n++) {
        ulonglong2 v = *(const ulonglong2*)&g_hs[base + p * DS + n * 4];
        h2[2*n] = v.x; h2[2*n+1] = v.y;
    }
    float Dh = Dp[hd];
    for (int t = 0; t < CH; t++) {
        float dA = sdA[t];
        float xv = __half2float(sx16[t * HD + p]);
        float s = sdt[t] * xv;
        u64 dA2 = f2pk(dA, dA), s2 = f2pk(s, s);
        u64 y2a = 0ull, y2b = 0ull;
        #pragma unroll
        for (int n = 0; n < 4; n++) {
            ulonglong2 Bq = *(const ulonglong2*)&sB[t * DS + n * 4];
            ulonglong2 Cq = *(const ulonglong2*)&sC[t * DS + n * 4];
            h2[2*n]   = f2fma(dA2, h2[2*n],   f2mul(s2, Bq.x));
            h2[2*n+1] = f2fma(dA2, h2[2*n+1], f2mul(s2, Bq.y));
            y2a = f2fma(h2[2*n],   Cq.x, y2a);
            y2b = f2fma(h2[2*n+1], Cq.y, y2b);
        }
        float y = f2sum(f2add(y2a, y2b));
        g_y[((size_t)(b * LEN + t0 + t)) * DI + hd * HD + p] = y + Dh * xv;
    }
}

// ---------------- gating + RMSNorm -> fp16 -----------------------------------
__global__ void k_gate(const float* __restrict__ gnw) {
    int row = blockIdx.x, tid = threadIdx.x;
    const float* yr = g_y  + (size_t)row * DI;
    const float* zr = g_zx + (size_t)row * DP;
    float gv[6];
    float sq = 0.f;
    #pragma unroll
    for (int i = 0; i < 6; i++) {
        int cc = tid + 256 * i;
        float z = zr[cc];
        float g = yr[cc] * (z * fsigmoid(z));
        gv[i] = g;
        sq += g * g;
    }
    __shared__ float sh[8];
    #pragma unroll
    for (int m = 16; m; m >>= 1) sq += __shfl_xor_sync(0xffffffffu, sq, m);
    if ((tid & 31) == 0) sh[tid >> 5] = sq;
    __syncthreads();
    if (tid < 32) {
        float a = (tid < 8) ? sh[tid] : 0.f;
        #pragma unroll
        for (int m = 4; m; m >>= 1) a += __shfl_xor_sync(0xffffffffu, a, m);
        if (tid == 0) sh[0] = a;
    }
    __syncthreads();
    float inv = rsqrtf(sh[0] * (1.f / DI) + 1e-5f);
    size_t base = (size_t)row * DI;
    #pragma unroll
    for (int i = 0; i < 6; i++) {
        int cc = tid + 256 * i;
        g_g16[base + cc] = __float2half_rn(gv[i] * inv * gnw[cc]);
    }
}

// ---------------- launcher ---------------------------------------------------
extern "C" void kernel_launch(void* const* d_in, const int* in_sizes, int n_in,
                              void* d_out, int out_size) {
    const float* x       = (const float*)d_in[0];
    const float* ln_w    = (const float*)d_in[1];
    const float* ln_b    = (const float*)d_in[2];
    const float* W_in    = (const float*)d_in[3];
    const float* conv_w  = (const float*)d_in[4];
    const float* conv_b  = (const float*)d_in[5];
    const float* dt_bias = (const float*)d_in[6];
    const float* A_log   = (const float*)d_in[7];
    const float* Dv      = (const float*)d_in[8];
    const float* gnw     = (const float*)d_in[9];
    const float* W_out   = (const float*)d_in[10];
    float* out = (float*)d_out;

    __half *pu, *pw1, *pg, *pw2;
    float *pzx;
    cudaGetSymbolAddress((void**)&pzx, g_zx);
    cudaGetSymbolAddress((void**)&pu,  g_u16);
    cudaGetSymbolAddress((void**)&pw1, g_W1);
    cudaGetSymbolAddress((void**)&pg,  g_g16);
    cudaGetSymbolAddress((void**)&pw2, g_W2);

    cudaFuncSetAttribute(k_gemm_h, cudaFuncAttributeMaxDynamicSharedMemorySize, GSMEM);

    k_cvt2<<<(W1PAD + W2N + 255)/256, 256>>>(W_in, W_out);
    k_ln<<<TT, 256>>>(x, ln_w, ln_b);
    k_gemm_h<<<dim3(NP1/128, TT/128), 256, GSMEM>>>(
        pu, pw1, pzx, nullptr, TT, DP, DM);
    k_dtda<<<(TT * NH + 255) / 256, 256>>>(dt_bias, A_log);
    k_conv<<<dim3(CD/CC, TT/CT), 256>>>(conv_w, conv_b);
    k_scan1<<<dim3(NC, NH, BSZ), 64>>>();
    k_scan2<<<dim3(4, BSZ * NH), 256>>>();
    k_scan3<<<dim3(NC, NH, BSZ), 64>>>(Dv);
    k_gate<<<TT, 256>>>(gnw);
    k_gemm_h<<<dim3(DM/128, TT/128), 256, GSMEM>>>(
        pg, pw2, out, x, TT, DM, DI);
}

// round 17
// speedup vs baseline: 1.5847x; 1.0091x over previous
#include <cuda_runtime.h>
#include <cuda_fp16.h>
#include <math.h>
#include <stdint.h>

#define BSZ 2
#define LEN 4096
#define TT (BSZ*LEN)          // 8192 tokens
#define DM 768
#define DI 1536
#define DS 16
#define NH 24
#define HD 64
#define CD 1568               // DI + 2*DS
#define DP 3128               // 2*DI + 2*DS + NH
#define NP1 3200              // DP padded to 128
#define NC 64                 // chunks
#define CH 64                 // chunk length (LEN/NC)
#define HPB 4                 // heads per scan block

// ---------------- scratch (static device arrays; no runtime alloc) ----------
__device__ __align__(16) float g_zx[(size_t)TT*DP];
__device__ __align__(16) float g_xbc[(size_t)TT*CD];
__device__ float g_dt[TT*NH];
__device__ float g_dA[TT*NH];
__device__ __align__(16) float g_y[(size_t)TT*DI];
__device__ __align__(16) float g_hl[BSZ*NH*NC*HD*DS];
__device__ __align__(16) float g_hs[BSZ*NH*NC*HD*DS];
__device__ float g_P[BSZ*NH*NC];
// fp16 operand buffers (16B aligned for cp.async)
__device__ __align__(16) __half g_u16[(size_t)TT*DM];
__device__ __align__(16) __half g_W1[(size_t)NP1*DM];
__device__ __align__(16) __half g_g16[(size_t)TT*DI];
__device__ __align__(16) __half g_W2[(size_t)DM*DI];

// ---------------- packed f32x2 helpers (sm_103a FFMA2) ----------------------
typedef unsigned long long u64;
__device__ __forceinline__ u64 f2pk(float a, float b) {
    u64 r;
    asm("mov.b64 %0, {%1, %2};" : "=l"(r)
        : "r"(__float_as_uint(a)), "r"(__float_as_uint(b)));
    return r;
}
__device__ __forceinline__ u64 f2fma(u64 a, u64 b, u64 c) {
    u64 d;
    asm("fma.rn.f32x2 %0, %1, %2, %3;" : "=l"(d) : "l"(a), "l"(b), "l"(c));
    return d;
}
__device__ __forceinline__ u64 f2mul(u64 a, u64 b) {
    u64 d;
    asm("mul.rn.f32x2 %0, %1, %2;" : "=l"(d) : "l"(a), "l"(b));
    return d;
}
__device__ __forceinline__ u64 f2add(u64 a, u64 b) {
    u64 d;
    asm("add.rn.f32x2 %0, %1, %2;" : "=l"(d) : "l"(a), "l"(b));
    return d;
}
__device__ __forceinline__ float f2sum(u64 v) {
    unsigned lo, hi;
    asm("mov.b64 {%0, %1}, %2;" : "=r"(lo), "=r"(hi) : "l"(v));
    return __uint_as_float(lo) + __uint_as_float(hi);
}

__device__ __forceinline__ float fsigmoid(float v) {
    return 1.f / (1.f + __expf(-v));
}

// ---------------- weight convert (both weights, one launch) -----------------
#define W1PAD (NP1*DM)
#define W2N   (DM*DI)
__global__ void k_cvt2(const float* __restrict__ W1, const float* __restrict__ W2) {
    int i = blockIdx.x * 256 + threadIdx.x;
    if (i < W1PAD) {
        g_W1[i] = __float2half_rn((i < DP*DM) ? W1[i] : 0.f);
    } else if (i < W1PAD + W2N) {
        int j = i - W1PAD;
        g_W2[j] = __float2half_rn(W2[j]);
    }
}

// ---------------- layernorm -> fp16 ------------------------------------------
__global__ void k_ln(const float* __restrict__ x, const float* __restrict__ w,
                     const float* __restrict__ bb) {
    int row = blockIdx.x;
    int tid = threadIdx.x;
    const float* xr = x + (size_t)row * DM;
    float v0 = xr[tid], v1 = xr[tid + 256], v2 = xr[tid + 512];
    float s  = v0 + v1 + v2;
    float sq = v0*v0 + v1*v1 + v2*v2;
    __shared__ float sh[16];
    #pragma unroll
    for (int m = 16; m; m >>= 1) {
        s  += __shfl_xor_sync(0xffffffffu, s,  m);
        sq += __shfl_xor_sync(0xffffffffu, sq, m);
    }
    if ((tid & 31) == 0) { sh[tid >> 5] = s; sh[8 + (tid >> 5)] = sq; }
    __syncthreads();
    if (tid < 32) {
        float a  = (tid < 8) ? sh[tid]     : 0.f;
        float b2 = (tid < 8) ? sh[8 + tid] : 0.f;
        #pragma unroll
        for (int m = 4; m; m >>= 1) {
            a  += __shfl_xor_sync(0xffffffffu, a,  m);
            b2 += __shfl_xor_sync(0xffffffffu, b2, m);
        }
        if (tid == 0) { sh[0] = a; sh[8] = b2; }
    }
    __syncthreads();
    float mu  = sh[0] * (1.f / DM);
    float var = sh[8] * (1.f / DM) - mu * mu;
    float inv = rsqrtf(var + 1e-5f);
    size_t base = (size_t)row * DM;
    g_u16[base + tid]       = __float2half_rn((v0 - mu) * inv * w[tid]       + bb[tid]);
    g_u16[base + tid + 256] = __float2half_rn((v1 - mu) * inv * w[tid + 256] + bb[tid + 256]);
    g_u16[base + tid + 512] = __float2half_rn((v2 - mu) * inv * w[tid + 512] + bb[tid + 512]);
}

// ============================================================================
// fp16 single-pass HMMA NT GEMM: C[M,N] = A[M,K]*B[N,K]^T (+R).
// CTA tile 128x128x32, 8 warps (warp tile 64x32), 4-stage cp.async, ldmatrix.x4.
// ============================================================================
#define SP 40                     // smem row pitch in halves (32 data + 8 pad)
#define A_ELE (128*SP)
#define OFF_A 0
#define OFF_B (A_ELE*2)
#define STAGE_B (2*A_ELE*2)       // 20480 bytes
#define NSTG 4
#define GSMEM (NSTG*STAGE_B)      // 81920 bytes

__device__ __forceinline__ uint32_t smaddr(const void* p) {
    return (uint32_t)__cvta_generic_to_shared(p);
}
#define CPA(d, s) asm volatile("cp.async.cg.shared.global [%0], [%1], 16;\n" :: "r"(d), "l"(s))
#define CPCOMMIT() asm volatile("cp.async.commit_group;\n")
#define CPWAIT2() asm volatile("cp.async.wait_group 2;\n")
#define LDSM4(r0,r1,r2,r3,a) asm volatile( \
    "ldmatrix.sync.aligned.m8n8.x4.shared.b16 {%0,%1,%2,%3}, [%4];\n" \
    : "=r"(r0),"=r"(r1),"=r"(r2),"=r"(r3) : "r"(a))
#define MMAH(d, a, b0, b1) \
  asm volatile("mma.sync.aligned.m16n8k16.row.col.f32.f16.f16.f32 " \
      "{%0,%1,%2,%3}, {%4,%5,%6,%7}, {%8,%9}, {%0,%1,%2,%3};\n" \
      : "+f"(d[0]), "+f"(d[1]), "+f"(d[2]), "+f"(d[3]) \
      : "r"(a[0]), "r"(a[1]), "r"(a[2]), "r"(a[3]), "r"(b0), "r"(b1))

__global__ void __launch_bounds__(256, 2)
k_gemm_h(const __half* __restrict__ A, const __half* __restrict__ B,
         float* __restrict__ C, const float* __restrict__ R,
         int M, int N, int K) {
    extern __shared__ __half sm[];
    const int tid = threadIdx.x;
    const int warp = tid >> 5, lane = tid & 31;
    const int wm = (warp & 1) * 64;
    const int wn = (warp >> 1) * 32;
    const int bm = blockIdx.y * 128, bn = blockIdx.x * 128;
    const int nIter = K >> 5;
    const uint32_t smb = smaddr(sm);

    const int a_r = lane & 15, a_k = (lane >> 4) << 3;
    const int b_r = (lane & 7) + ((lane >> 4) << 3);
    const int b_k = ((lane >> 3) & 1) << 3;

    float acc[4][4][4];
    #pragma unroll
    for (int i = 0; i < 4; i++)
        #pragma unroll
        for (int j = 0; j < 4; j++)
            #pragma unroll
            for (int k = 0; k < 4; k++) acc[i][j][k] = 0.f;

    #define ISSUE(kt) do {                                                     \
        int _b = (kt) & (NSTG - 1), _k = (kt) << 5;                            \
        uint32_t _sb = smb + (uint32_t)_b * STAGE_B;                           \
        _Pragma("unroll")                                                      \
        for (int _i = 0; _i < 2; _i++) {                                       \
            int _idx = tid + 256 * _i;                                         \
            int _r = _idx >> 2, _c = (_idx & 3) << 3;                          \
            uint32_t _d = (uint32_t)(_r * SP + _c) * 2;                        \
            CPA(_sb + OFF_A + _d, A + (size_t)(bm + _r) * K + _k + _c);        \
            CPA(_sb + OFF_B + _d, B + (size_t)(bn + _r) * K + _k + _c);        \
        }                                                                      \
        CPCOMMIT();                                                            \
    } while (0)

    ISSUE(0);
    ISSUE(1);
    ISSUE(2);

    for (int kt = 0; kt < nIter; kt++) {
        CPWAIT2();
        __syncthreads();
        const int s = kt & (NSTG - 1);
        const uint32_t sb = smb + (uint32_t)s * STAGE_B;

        #pragma unroll
        for (int sub = 0; sub < 32; sub += 16) {
            unsigned bh[2][4];
            #pragma unroll
            for (int p = 0; p < 2; p++) {
                uint32_t ba = sb + OFF_B +
                    (uint32_t)((wn + p*16 + b_r) * SP + sub + b_k) * 2;
                LDSM4(bh[p][0], bh[p][1], bh[p][2], bh[p][3], ba);
            }
            #pragma unroll
            for (int mt = 0; mt < 4; mt++) {
                unsigned ah[4];
                uint32_t aa = sb + OFF_A +
                    (uint32_t)((wm + mt*16 + a_r) * SP + sub + a_k) * 2;
                LDSM4(ah[0], ah[1], ah[2], ah[3], aa);
                #pragma unroll
                for (int p = 0; p < 2; p++) {
                    MMAH(acc[mt][2*p],   ah, bh[p][0], bh[p][1]);
                    MMAH(acc[mt][2*p+1], ah, bh[p][2], bh[p][3]);
                }
            }
        }

        int nk = kt + 3;
        if (nk < nIter) { ISSUE(nk); }
        else            { CPCOMMIT(); }
    }

    const int g = lane >> 2, q = lane & 3;
    #pragma unroll
    for (int mt = 0; mt < 4; mt++) {
        int row0 = bm + wm + mt * 16 + g;
        #pragma unroll
        for (int nt = 0; nt < 4; nt++) {
            int col = bn + wn + nt * 8 + 2 * q;
            if (col < N) {
                float2 v0, v1;
                v0.x = acc[mt][nt][0]; v0.y = acc[mt][nt][1];
                v1.x = acc[mt][nt][2]; v1.y = acc[mt][nt][3];
                if (R) {
                    const float* rr0 = R + (size_t)row0 * N + col;
                    const float* rr1 = R + (size_t)(row0 + 8) * N + col;
                    v0.x += rr0[0]; v0.y += rr0[1];
                    v1.x += rr1[0]; v1.y += rr1[1];
                }
                *(float2*)(C + (size_t)row0 * N + col) = v0;
                *(float2*)(C + (size_t)(row0 + 8) * N + col) = v1;
            }
        }
    }
    #undef ISSUE
}

// ---------------- dt = softplus(raw + bias), dA = exp(dt * -exp(A_log)) -----
__global__ void k_dtda(const float* __restrict__ dtb, const float* __restrict__ alog) {
    int i = blockIdx.x * 256 + threadIdx.x;
    if (i >= TT * NH) return;
    int h = i % NH, t = i / NH;
    float xv = g_zx[(size_t)t * DP + (DI + CD) + h] + dtb[h];
    float dt = (xv > 20.f) ? xv : __logf(1.f + __expf(xv));
    float A = -__expf(alog[h]);
    g_dt[i] = dt;
    g_dA[i] = __expf(dt * A);
}

// ---------------- causal depthwise conv(4): smem-tiled -----------------------
#define CT 32
#define CC 224
__global__ void __launch_bounds__(256)
k_conv(const float* __restrict__ cw, const float* __restrict__ cb) {
    __shared__ float sx[(CT + 3) * CC];
    __shared__ float swt[CC * 4];
    __shared__ float sbi[CC];
    int c0 = blockIdx.x * CC;
    int tblk = blockIdx.y;
    int b = (tblk * CT) / LEN;
    int l0 = (tblk * CT) % LEN;
    int tid = threadIdx.x;

    for (int i = tid; i < CC * 4; i += 256) swt[i] = cw[c0 * 4 + i];
    for (int i = tid; i < CC; i += 256)     sbi[i] = cb[c0 + i];
    for (int i = tid; i < (CT + 3) * CC; i += 256) {
        int r = i / CC, c = i % CC;
        int l = l0 - 3 + r;
        sx[i] = (l >= 0) ? g_zx[((size_t)(b * LEN + l)) * DP + DI + c0 + c] : 0.f;
    }
    __syncthreads();

    for (int i = tid; i < CT * CC; i += 256) {
        int t = i / CC, c = i % CC;
        const float* w4 = &swt[c * 4];
        float acc = sbi[c];
        acc = fmaf(sx[(t + 0) * CC + c], w4[0], acc);
        acc = fmaf(sx[(t + 1) * CC + c], w4[1], acc);
        acc = fmaf(sx[(t + 2) * CC + c], w4[2], acc);
        acc = fmaf(sx[(t + 3) * CC + c], w4[3], acc);
        g_xbc[((size_t)(b * LEN + l0 + t)) * CD + c0 + c] = acc * fsigmoid(acc);
    }
}

// ---------------- scan phase 1: 4 heads/block, fp16 x tile, f32x2 -----------
__global__ void __launch_bounds__(256)
k_scan1() {
    int c = blockIdx.x, hg = blockIdx.y, b = blockIdx.z;
    int tid = threadIdx.x;
    int sub = tid >> 6, p = tid & 63;
    int hd = hg * HPB + sub;
    __shared__ __half sx16[CH * HPB * HD];       // [t][256] contiguous cols
    __shared__ __align__(16) float sB[CH * DS];
    __shared__ float sdt[HPB][CH];
    __shared__ float sdA[HPB][CH];
    int t0 = c * CH;
    size_t rb = ((size_t)(b * LEN + t0)) * CD;
    for (int idx = tid; idx < CH * 256; idx += 256) {
        int t = idx >> 8, col = idx & 255;
        sx16[idx] = __float2half_rn(g_xbc[rb + (size_t)t * CD + hg * 256 + col]);
    }
    for (int idx = tid; idx < CH * DS; idx += 256) {
        int t = idx >> 4, n = idx & 15;
        sB[idx] = g_xbc[rb + (size_t)t * CD + DI + n];
    }
    {
        int tg = (b * LEN + t0 + p) * NH + hd;
        sdt[sub][p] = g_dt[tg];
        sdA[sub][p] = g_dA[tg];
    }
    __syncthreads();
    u64 h2[8];
    #pragma unroll
    for (int n = 0; n < 8; n++) h2[n] = 0ull;
    float run = 1.f;
    const __half* xcol = sx16 + sub * 64 + p;
    for (int t = 0; t < CH; t++) {
        float dA = sdA[sub][t];
        float s = sdt[sub][t] * __half2float(xcol[t * 256]);
        run *= dA;
        u64 dA2 = f2pk(dA, dA), s2 = f2pk(s, s);
        #pragma unroll
        for (int n = 0; n < 4; n++) {
            ulonglong2 Bq = *(const ulonglong2*)&sB[t * DS + n * 4];
            h2[2*n]   = f2fma(dA2, h2[2*n],   f2mul(s2, Bq.x));
            h2[2*n+1] = f2fma(dA2, h2[2*n+1], f2mul(s2, Bq.y));
        }
    }
    size_t base = ((size_t)((b * NH + hd) * NC + c)) * (HD * DS);
    #pragma unroll
    for (int n = 0; n < 4; n++) {
        ulonglong2 v; v.x = h2[2*n]; v.y = h2[2*n+1];
        *(ulonglong2*)&g_hl[base + p * DS + n * 4] = v;
    }
    if (p == 0) g_P[(b * NH + hd) * NC + c] = run;
}

// ---------------- scan phase 2: prefix over chunks, 1 elem/thread -----------
__global__ void __launch_bounds__(256)
k_scan2() {
    int e = blockIdx.x * 256 + threadIdx.x;   // 0..1023
    int bh = blockIdx.y;                       // 0..47
    __shared__ float sP[NC];
    if (threadIdx.x < NC) sP[threadIdx.x] = g_P[bh * NC + threadIdx.x];
    __syncthreads();
    float H = 0.f;
    #pragma unroll 8
    for (int c = 0; c < NC; c++) {
        size_t base = ((size_t)(bh * NC + c)) * (HD * DS);
        g_hs[base + e] = H;
        H = fmaf(sP[c], H, g_hl[base + e]);
    }
}

// ---------------- scan phase 3: 4 heads/block, dual y chains ----------------
__global__ void __launch_bounds__(256)
k_scan3(const float* __restrict__ Dp) {
    int c = blockIdx.x, hg = blockIdx.y, b = blockIdx.z;
    int tid = threadIdx.x;
    int sub = tid >> 6, p = tid & 63;
    int hd = hg * HPB + sub;
    __shared__ __half sx16[CH * HPB * HD];
    __shared__ __align__(16) float sB[CH * DS];
    __shared__ __align__(16) float sC[CH * DS];
    __shared__ float sdt[HPB][CH];
    __shared__ float sdA[HPB][CH];
    int t0 = c * CH;
    size_t rb = ((size_t)(b * LEN + t0)) * CD;
    for (int idx = tid; idx < CH * 256; idx += 256) {
        int t = idx >> 8, col = idx & 255;
        sx16[idx] = __float2half_rn(g_xbc[rb + (size_t)t * CD + hg * 256 + col]);
    }
    for (int idx = tid; idx < CH * DS; idx += 256) {
        int t = idx >> 4, n = idx & 15;
        sB[idx] = g_xbc[rb + (size_t)t * CD + DI + n];
        sC[idx] = g_xbc[rb + (size_t)t * CD + DI + DS + n];
    }
    {
        int tg = (b * LEN + t0 + p) * NH + hd;
        sdt[sub][p] = g_dt[tg];
        sdA[sub][p] = g_dA[tg];
    }
    __syncthreads();
    size_t base = ((size_t)((b * NH + hd) * NC + c)) * (HD * DS);
    u64 h2[8];
    #pragma unroll
    for (int n = 0; n < 4; n++) {
        ulonglong2 v = *(const ulonglong2*)&g_hs[base + p * DS + n * 4];
        h2[2*n] = v.x; h2[2*n+1] = v.y;
    }
    float Dh = Dp[hd];
    const __half* xcol = sx16 + sub * 64 + p;
    for (int t = 0; t < CH; t++) {
        float dA = sdA[sub][t];
        float xv = __half2float(xcol[t * 256]);
        float s = sdt[sub][t] * xv;
        u64 dA2 = f2pk(dA, dA), s2 = f2pk(s, s);
        u64 y2a = 0ull, y2b = 0ull;
        #pragma unroll
        for (int n = 0; n < 4; n++) {
            ulonglong2 Bq = *(const ulonglong2*)&sB[t * DS + n * 4];
            ulonglong2 Cq = *(const ulonglong2*)&sC[t * DS + n * 4];
            h2[2*n]   = f2fma(dA2, h2[2*n],   f2mul(s2, Bq.x));
            h2[2*n+1] = f2fma(dA2, h2[2*n+1], f2mul(s2, Bq.y));
            y2a = f2fma(h2[2*n],   Cq.x, y2a);
            y2b = f2fma(h2[2*n+1], Cq.y, y2b);
        }
        float y = f2sum(f2add(y2a, y2b));
        g_y[((size_t)(b * LEN + t0 + t)) * DI + hd * HD + p] = y + Dh * xv;
    }
}

// ---------------- gating + RMSNorm -> fp16 -----------------------------------
__global__ void k_gate(const float* __restrict__ gnw) {
    int row = blockIdx.x, tid = threadIdx.x;
    const float* yr = g_y  + (size_t)row * DI;
    const float* zr = g_zx + (size_t)row * DP;
    float gv[6];
    float sq = 0.f;
    #pragma unroll
    for (int i = 0; i < 6; i++) {
        int cc = tid + 256 * i;
        float z = zr[cc];
        float g = yr[cc] * (z * fsigmoid(z));
        gv[i] = g;
        sq += g * g;
    }
    __shared__ float sh[8];
    #pragma unroll
    for (int m = 16; m; m >>= 1) sq += __shfl_xor_sync(0xffffffffu, sq, m);
    if ((tid & 31) == 0) sh[tid >> 5] = sq;
    __syncthreads();
    if (tid < 32) {
        float a = (tid < 8) ? sh[tid] : 0.f;
        #pragma unroll
        for (int m = 4; m; m >>= 1) a += __shfl_xor_sync(0xffffffffu, a, m);
        if (tid == 0) sh[0] = a;
    }
    __syncthreads();
    float inv = rsqrtf(sh[0] * (1.f / DI) + 1e-5f);
    size_t base = (size_t)row * DI;
    #pragma unroll
    for (int i = 0; i < 6; i++) {
        int cc = tid + 256 * i;
        g_g16[base + cc] = __float2half_rn(gv[i] * inv * gnw[cc]);
    }
}

// ---------------- launcher ---------------------------------------------------
extern "C" void kernel_launch(void* const* d_in, const int* in_sizes, int n_in,
                              void* d_out, int out_size) {
    const float* x       = (const float*)d_in[0];
    const float* ln_w    = (const float*)d_in[1];
    const float* ln_b    = (const float*)d_in[2];
    const float* W_in    = (const float*)d_in[3];
    const float* conv_w  = (const float*)d_in[4];
    const float* conv_b  = (const float*)d_in[5];
    const float* dt_bias = (const float*)d_in[6];
    const float* A_log   = (const float*)d_in[7];
    const float* Dv      = (const float*)d_in[8];
    const float* gnw     = (const float*)d_in[9];
    const float* W_out   = (const float*)d_in[10];
    float* out = (float*)d_out;

    __half *pu, *pw1, *pg, *pw2;
    float *pzx;
    cudaGetSymbolAddress((void**)&pzx, g_zx);
    cudaGetSymbolAddress((void**)&pu,  g_u16);
    cudaGetSymbolAddress((void**)&pw1, g_W1);
    cudaGetSymbolAddress((void**)&pg,  g_g16);
    cudaGetSymbolAddress((void**)&pw2, g_W2);

    cudaFuncSetAttribute(k_gemm_h, cudaFuncAttributeMaxDynamicSharedMemorySize, GSMEM);

    k_cvt2<<<(W1PAD + W2N + 255)/256, 256>>>(W_in, W_out);
    k_ln<<<TT, 256>>>(x, ln_w, ln_b);
    k_gemm_h<<<dim3(NP1/128, TT/128), 256, GSMEM>>>(
        pu, pw1, pzx, nullptr, TT, DP, DM);
    k_dtda<<<(TT * NH + 255) / 256, 256>>>(dt_bias, A_log);
    k_conv<<<dim3(CD/CC, TT/CT), 256>>>(conv_w, conv_b);
    k_scan1<<<dim3(NC, NH/HPB, BSZ), 256>>>();
    k_scan2<<<dim3(4, BSZ * NH), 256>>>();
    k_scan3<<<dim3(NC, NH/HPB, BSZ), 256>>>(Dv);
    k_gate<<<TT, 256>>>(gnw);
    k_gemm_h<<<dim3(DM/128, TT/128), 256, GSMEM>>>(
        pg, pw2, out, x, TT, DM, DI);
}